// round 1
// baseline (speedup 1.0000x reference)
#include <cuda_runtime.h>
#include <math.h>

#define NT      512
#define D       128
#define PN      30
#define NHH     16
#define SEQ     720
#define CIN     321
#define SCALE   0.35355339059327373f   // 8^-0.5

// smem floats: x(3840) pred(3840) k(3840) v(3840) scratch(3840) scores(14400) red(40)
#define SMEM_FLOATS (3840*5 + 14400 + 40)
#define SMEM_BYTES  (SMEM_FLOATS * 4)

__device__ __forceinline__ void ln_rows(float* buf, const float* __restrict__ g,
                                        const float* __restrict__ b) {
    int warp = threadIdx.x >> 5, lane = threadIdx.x & 31;
    float g0 = g[lane], g1 = g[lane+32], g2 = g[lane+64], g3 = g[lane+96];
    float b0 = b[lane], b1 = b[lane+32], b2 = b[lane+64], b3 = b[lane+96];
    for (int r = warp; r < PN; r += NT/32) {
        float* row = buf + r*D;
        float v0 = row[lane], v1 = row[lane+32], v2 = row[lane+64], v3 = row[lane+96];
        float s = v0+v1+v2+v3;
        float q = v0*v0 + v1*v1 + v2*v2 + v3*v3;
        #pragma unroll
        for (int o = 16; o; o >>= 1) {
            s += __shfl_xor_sync(0xffffffffu, s, o);
            q += __shfl_xor_sync(0xffffffffu, q, o);
        }
        float mu  = s * (1.f/128.f);
        float var = q * (1.f/128.f) - mu*mu;
        float rr  = rsqrtf(var + 1e-5f);
        row[lane]    = (v0-mu)*rr*g0 + b0;
        row[lane+32] = (v1-mu)*rr*g1 + b1;
        row[lane+64] = (v2-mu)*rr*g2 + b2;
        row[lane+96] = (v3-mu)*rr*g3 + b3;
    }
}

__global__ __launch_bounds__(NT, 1)
void ts_kernel(const float* __restrict__ z,
               const float* __restrict__ WPw, const float* __restrict__ WPb,
               const float* __restrict__ PE,  const float* __restrict__ dummies,
               const float* __restrict__ Wq,  const float* __restrict__ bq,
               const float* __restrict__ Wk,  const float* __restrict__ bk,
               const float* __restrict__ Wv,  const float* __restrict__ bv,
               const float* __restrict__ Wo,  const float* __restrict__ bo,
               const float* __restrict__ g1,  const float* __restrict__ be1,
               const float* __restrict__ W1,  const float* __restrict__ b1,
               const float* __restrict__ W2,  const float* __restrict__ b2,
               const float* __restrict__ g2,  const float* __restrict__ be2,
               const float* __restrict__ Pw,  const float* __restrict__ Pb,
               float* __restrict__ out)
{
    extern __shared__ float sm[];
    float* xb  = sm;            // 3840 : encoder tokens x
    float* pr  = xb  + 3840;    // 3840 : pred tokens
    float* kb  = pr  + 3840;    // 3840 : K
    float* vb  = kb  + 3840;    // 3840 : V
    float* sc  = vb  + 3840;    // 3840 : scratch (zn -> dummies -> q -> o -> ag)
    float* sco = sc  + 3840;    // 14400: raw accumulated scores [h][p][t]
    float* red = sco + 14400;   // 40

    const int tid = threadIdx.x;
    const int blk = blockIdx.x;              // b*CIN + c
    const int ch  = blk % CIN;
    const float* zr = z + (size_t)blk * SEQ;

    // ---------------- instance stats over SEQ ----------------
    float s1 = 0.f, s2 = 0.f;
    for (int i = tid; i < SEQ; i += NT) { float v = zr[i]; s1 += v; s2 += v*v; }
    #pragma unroll
    for (int o = 16; o; o >>= 1) {
        s1 += __shfl_xor_sync(0xffffffffu, s1, o);
        s2 += __shfl_xor_sync(0xffffffffu, s2, o);
    }
    {
        int warp = tid >> 5, lane = tid & 31;
        if (lane == 0) { red[warp] = s1; red[16 + warp] = s2; }
    }
    __syncthreads();
    if (tid == 0) {
        float S1 = 0.f, S2 = 0.f;
        #pragma unroll
        for (int w = 0; w < NT/32; w++) { S1 += red[w]; S2 += red[16 + w]; }
        float mu  = S1 / (float)SEQ;
        float var = S2 / (float)SEQ - mu*mu;
        float sd  = sqrtf(var + 1e-5f);
        red[32] = mu; red[33] = 1.f/sd; red[34] = sd;
    }
    __syncthreads();
    const float mu = red[32], rstd = red[33];

    // zn -> scratch ; zero scores
    for (int i = tid; i < SEQ; i += NT) sc[i] = (zr[i] - mu) * rstd;
    for (int i = tid; i < NHH*PN*PN; i += NT) sco[i] = 0.f;
    __syncthreads();

    const int e  = tid & 127;   // output feature
    const int pg = tid >> 7;    // row group 0..3

    // ---------------- patch embedding: x and pred ----------------
    {
        float w[24];
        #pragma unroll
        for (int p = 0; p < 24; p++) w[p] = WPw[e*24 + p];
        const float bias = WPb[e];
        for (int s = pg; s < PN; s += 4) {
            float acc = bias + PE[s*D + e];
            #pragma unroll
            for (int p = 0; p < 24; p++) acc += sc[s*24 + p] * w[p];
            xb[s*D + e] = acc;
        }
        __syncthreads();
        const float* dm = dummies + (size_t)ch * PN * 24;
        for (int i = tid; i < PN*24; i += NT) sc[i] = dm[i];
        __syncthreads();
        for (int s = pg; s < PN; s += 4) {
            float acc = bias;
            #pragma unroll
            for (int p = 0; p < 24; p++) acc += sc[s*24 + p] * w[p];
            pr[s*D + e] = acc;
        }
    }
    __syncthreads();

    // ---------------- transformer layers ----------------
    #pragma unroll 1
    for (int L = 0; L < 3; L++) {
        // ---- K and V (fused weight pass over x) ----
        {
            const float4* wk4 = (const float4*)(Wk + (size_t)L*D*D + e*D);
            const float4* wv4 = (const float4*)(Wv + (size_t)L*D*D + e*D);
            const float bke = bk[L*D + e], bve = bv[L*D + e];
            float ak[8], av[8];
            #pragma unroll
            for (int j = 0; j < 8; j++) { ak[j] = bke; av[j] = bve; }
            #pragma unroll 4
            for (int kk = 0; kk < 32; kk++) {
                float4 a = wk4[kk], b4 = wv4[kk];
                #pragma unroll
                for (int j = 0; j < 8; j++) {
                    int t = pg + 4*j;
                    if (t < PN) {
                        float4 xx = *(const float4*)(xb + t*D + kk*4);
                        ak[j] += xx.x*a.x  + xx.y*a.y  + xx.z*a.z  + xx.w*a.w;
                        av[j] += xx.x*b4.x + xx.y*b4.y + xx.z*b4.z + xx.w*b4.w;
                    }
                }
            }
            #pragma unroll
            for (int j = 0; j < 8; j++) {
                int t = pg + 4*j;
                if (t < PN) { kb[t*D+e] = ak[j]; vb[t*D+e] = av[j]; }
            }
        }
        // ---- Q into scratch ----
        {
            const float4* wq4 = (const float4*)(Wq + (size_t)L*D*D + e*D);
            const float bqe = bq[L*D + e];
            float aq[8];
            #pragma unroll
            for (int j = 0; j < 8; j++) aq[j] = bqe;
            #pragma unroll 4
            for (int kk = 0; kk < 32; kk++) {
                float4 a = wq4[kk];
                #pragma unroll
                for (int j = 0; j < 8; j++) {
                    int t = pg + 4*j;
                    if (t < PN) {
                        float4 xx = *(const float4*)(pr + t*D + kk*4);
                        aq[j] += xx.x*a.x + xx.y*a.y + xx.z*a.z + xx.w*a.w;
                    }
                }
            }
            #pragma unroll
            for (int j = 0; j < 8; j++) {
                int t = pg + 4*j;
                if (t < PN) sc[t*D+e] = aq[j];
            }
        }
        __syncthreads();

        // ---- scores += scale * q.k  (raw accumulation across layers) ----
        for (int idx = tid; idx < NHH*PN*PN; idx += NT) {
            int h = idx / (PN*PN);
            int r = idx % (PN*PN);
            int p = r / PN, t = r % PN;
            const float* qp = sc + p*D + h*8;
            const float* kp = kb + t*D + h*8;
            float a = 0.f;
            #pragma unroll
            for (int j = 0; j < 8; j++) a += qp[j]*kp[j];
            sco[idx] += a * SCALE;
        }
        __syncthreads();

        // ---- softmax (registers only) + attn@V -> o into scratch ----
        if (tid < NHH*PN) {
            int h = tid / PN, p = tid % PN;
            const float* srow = sco + h*PN*PN + p*PN;
            float m = -1e30f;
            #pragma unroll
            for (int t = 0; t < PN; t++) m = fmaxf(m, srow[t]);
            float w[PN]; float ss = 0.f;
            #pragma unroll
            for (int t = 0; t < PN; t++) { w[t] = __expf(srow[t]-m); ss += w[t]; }
            float inv = 1.f/ss;
            #pragma unroll
            for (int j = 0; j < 8; j++) {
                float a = 0.f;
                #pragma unroll
                for (int t = 0; t < PN; t++) a += w[t] * vb[t*D + h*8 + j];
                sc[p*D + h*8 + j] = a * inv;
            }
        }
        __syncthreads();

        // ---- O projection + residual into pred ----
        {
            const float4* wo4 = (const float4*)(Wo + (size_t)L*D*D + e*D);
            const float boe = bo[L*D + e];
            float ao[8];
            #pragma unroll
            for (int j = 0; j < 8; j++) ao[j] = boe;
            #pragma unroll 4
            for (int kk = 0; kk < 32; kk++) {
                float4 a = wo4[kk];
                #pragma unroll
                for (int j = 0; j < 8; j++) {
                    int t = pg + 4*j;
                    if (t < PN) {
                        float4 oo = *(const float4*)(sc + t*D + kk*4);
                        ao[j] += oo.x*a.x + oo.y*a.y + oo.z*a.z + oo.w*a.w;
                    }
                }
            }
            #pragma unroll
            for (int j = 0; j < 8; j++) {
                int t = pg + 4*j;
                if (t < PN) pr[t*D+e] += ao[j];
            }
        }
        __syncthreads();
        ln_rows(pr, g1 + L*D, be1 + L*D);
        __syncthreads();

        // ---- FFN up (a and gate halves fused) -> ag into scratch ----
        {
            const float4* w1a = (const float4*)(W1 + (size_t)L*256*D + e*D);
            const float4* w1g = (const float4*)(W1 + (size_t)L*256*D + (e+128)*D);
            const float ba = b1[L*256 + e], bg = b1[L*256 + 128 + e];
            float aa[8], ag[8];
            #pragma unroll
            for (int j = 0; j < 8; j++) { aa[j] = ba; ag[j] = bg; }
            #pragma unroll 4
            for (int kk = 0; kk < 32; kk++) {
                float4 wa = w1a[kk], wg = w1g[kk];
                #pragma unroll
                for (int j = 0; j < 8; j++) {
                    int t = pg + 4*j;
                    if (t < PN) {
                        float4 pp = *(const float4*)(pr + t*D + kk*4);
                        aa[j] += pp.x*wa.x + pp.y*wa.y + pp.z*wa.z + pp.w*wa.w;
                        ag[j] += pp.x*wg.x + pp.y*wg.y + pp.z*wg.z + pp.w*wg.w;
                    }
                }
            }
            #pragma unroll
            for (int j = 0; j < 8; j++) {
                int t = pg + 4*j;
                if (t < PN) {
                    float gv  = ag[j];
                    float gel = 0.5f * gv * (1.f + erff(gv * 0.70710678118654752f));
                    sc[t*D+e] = aa[j] * gel;
                }
            }
        }
        __syncthreads();

        // ---- FFN down + residual into pred ----
        {
            const float4* w24 = (const float4*)(W2 + (size_t)L*D*D + e*D);
            const float b2e = b2[L*D + e];
            float a2[8];
            #pragma unroll
            for (int j = 0; j < 8; j++) a2[j] = b2e;
            #pragma unroll 4
            for (int kk = 0; kk < 32; kk++) {
                float4 a = w24[kk];
                #pragma unroll
                for (int j = 0; j < 8; j++) {
                    int t = pg + 4*j;
                    if (t < PN) {
                        float4 hh = *(const float4*)(sc + t*D + kk*4);
                        a2[j] += hh.x*a.x + hh.y*a.y + hh.z*a.z + hh.w*a.w;
                    }
                }
            }
            #pragma unroll
            for (int j = 0; j < 8; j++) {
                int t = pg + 4*j;
                if (t < PN) pr[t*D+e] += a2[j];
            }
        }
        __syncthreads();
        ln_rows(pr, g2 + L*D, be2 + L*D);
        __syncthreads();
    }

    // ---------------- output head + de-normalization ----------------
    const float sd = red[34];
    for (int idx = tid; idx < PN*24; idx += NT) {
        int p = idx / 24, pl = idx % 24;
        const float4* pw = (const float4*)(Pw + pl*D);
        const float4* pp = (const float4*)(pr + p*D);
        float acc = Pb[pl];
        #pragma unroll
        for (int kk = 0; kk < 32; kk++) {
            float4 a = pw[kk], x4 = pp[kk];
            acc += x4.x*a.x + x4.y*a.y + x4.z*a.z + x4.w*a.w;
        }
        out[(size_t)blk*SEQ + idx] = acc * sd + mu;
    }
}

extern "C" void kernel_launch(void* const* d_in, const int* in_sizes, int n_in,
                              void* d_out, int out_size)
{
    (void)in_sizes; (void)n_in; (void)out_size;
    cudaFuncSetAttribute(ts_kernel, cudaFuncAttributeMaxDynamicSharedMemorySize, SMEM_BYTES);
    ts_kernel<<<16*CIN, NT, SMEM_BYTES>>>(
        (const float*)d_in[0],  (const float*)d_in[1],  (const float*)d_in[2],
        (const float*)d_in[3],  (const float*)d_in[4],  (const float*)d_in[5],
        (const float*)d_in[6],  (const float*)d_in[7],  (const float*)d_in[8],
        (const float*)d_in[9],  (const float*)d_in[10], (const float*)d_in[11],
        (const float*)d_in[12], (const float*)d_in[13], (const float*)d_in[14],
        (const float*)d_in[15], (const float*)d_in[16], (const float*)d_in[17],
        (const float*)d_in[18], (const float*)d_in[19], (const float*)d_in[20],
        (const float*)d_in[21], (const float*)d_in[22],
        (float*)d_out);
}

// round 3
// speedup vs baseline: 1.0587x; 1.0587x over previous
#include <cuda_runtime.h>
#include <math.h>

#define NT      512
#define D       128
#define PN      30
#define NHH     16
#define SEQ     720
#define CIN     321
#define SCALE   0.35355339059327373f   // 8^-0.5

// smem floats: x(3840) pred(3840) k(3840) v(3840) scratch(3840) scores(14400) red(40)
#define SMEM_FLOATS (3840*5 + 14400 + 40)
#define SMEM_BYTES  (SMEM_FLOATS * 4)

__device__ __forceinline__ void ln_rows(float* buf, const float* __restrict__ g,
                                        const float* __restrict__ b) {
    int warp = threadIdx.x >> 5, lane = threadIdx.x & 31;
    float g0 = g[lane], g1 = g[lane+32], g2 = g[lane+64], g3 = g[lane+96];
    float b0 = b[lane], b1 = b[lane+32], b2 = b[lane+64], b3 = b[lane+96];
    for (int r = warp; r < PN; r += NT/32) {
        float* row = buf + r*D;
        float v0 = row[lane], v1 = row[lane+32], v2 = row[lane+64], v3 = row[lane+96];
        float s = v0+v1+v2+v3;
        float q = v0*v0 + v1*v1 + v2*v2 + v3*v3;
        #pragma unroll
        for (int o = 16; o; o >>= 1) {
            s += __shfl_xor_sync(0xffffffffu, s, o);
            q += __shfl_xor_sync(0xffffffffu, q, o);
        }
        float mu  = s * (1.f/128.f);
        float var = q * (1.f/128.f) - mu*mu;
        float rr  = rsqrtf(var + 1e-5f);
        row[lane]    = (v0-mu)*rr*g0 + b0;
        row[lane+32] = (v1-mu)*rr*g1 + b1;
        row[lane+64] = (v2-mu)*rr*g2 + b2;
        row[lane+96] = (v3-mu)*rr*g3 + b3;
    }
}

__global__ __launch_bounds__(NT, 1)
void ts_kernel(const float* __restrict__ z,
               const float* __restrict__ WPw, const float* __restrict__ WPb,
               const float* __restrict__ PE,  const float* __restrict__ dummies,
               const float* __restrict__ Wq,  const float* __restrict__ bq,
               const float* __restrict__ Wk,  const float* __restrict__ bk,
               const float* __restrict__ Wv,  const float* __restrict__ bv,
               const float* __restrict__ Wo,  const float* __restrict__ bo,
               const float* __restrict__ g1,  const float* __restrict__ be1,
               const float* __restrict__ W1,  const float* __restrict__ b1,
               const float* __restrict__ W2,  const float* __restrict__ b2,
               const float* __restrict__ g2,  const float* __restrict__ be2,
               const float* __restrict__ Pw,  const float* __restrict__ Pb,
               float* __restrict__ out)
{
    extern __shared__ float sm[];
    float* xb  = sm;            // 3840 : encoder tokens x
    float* pr  = xb  + 3840;    // 3840 : pred tokens
    float* kb  = pr  + 3840;    // 3840 : K
    float* vb  = kb  + 3840;    // 3840 : V
    float* sc  = vb  + 3840;    // 3840 : scratch (zn -> dummies -> q -> o -> ag)
    float* sco = sc  + 3840;    // 14400: raw accumulated scores [h][p][t]
    float* red = sco + 14400;   // 40

    const int tid = threadIdx.x;
    const int blk = blockIdx.x;              // b*CIN + c
    const int ch  = blk % CIN;
    const float* zr = z + (size_t)blk * SEQ;

    // ---------------- instance stats over SEQ ----------------
    float s1 = 0.f, s2 = 0.f;
    for (int i = tid; i < SEQ; i += NT) { float v = zr[i]; s1 += v; s2 += v*v; }
    #pragma unroll
    for (int o = 16; o; o >>= 1) {
        s1 += __shfl_xor_sync(0xffffffffu, s1, o);
        s2 += __shfl_xor_sync(0xffffffffu, s2, o);
    }
    {
        int warp = tid >> 5, lane = tid & 31;
        if (lane == 0) { red[warp] = s1; red[16 + warp] = s2; }
    }
    __syncthreads();
    if (tid == 0) {
        float S1 = 0.f, S2 = 0.f;
        #pragma unroll
        for (int w = 0; w < NT/32; w++) { S1 += red[w]; S2 += red[16 + w]; }
        float mu  = S1 / (float)SEQ;
        float var = S2 / (float)SEQ - mu*mu;
        float sd  = sqrtf(var + 1e-5f);
        red[32] = mu; red[33] = 1.f/sd; red[34] = sd;
    }
    __syncthreads();
    const float mu = red[32], rstd = red[33];

    // zn -> scratch ; zero scores
    for (int i = tid; i < SEQ; i += NT) sc[i] = (zr[i] - mu) * rstd;
    for (int i = tid; i < NHH*PN*PN; i += NT) sco[i] = 0.f;
    __syncthreads();

    const int e  = tid & 127;   // output feature
    const int pg = tid >> 7;    // row group 0..3

    // ---------------- patch embedding: x and pred ----------------
    {
        float w[24];
        #pragma unroll
        for (int p = 0; p < 24; p++) w[p] = WPw[e*24 + p];
        const float bias = WPb[e];
        for (int s = pg; s < PN; s += 4) {
            float acc = bias + PE[s*D + e];
            #pragma unroll
            for (int p = 0; p < 24; p++) acc += sc[s*24 + p] * w[p];
            xb[s*D + e] = acc;
        }
        __syncthreads();
        const float* dm = dummies + (size_t)ch * PN * 24;
        for (int i = tid; i < PN*24; i += NT) sc[i] = dm[i];
        __syncthreads();
        for (int s = pg; s < PN; s += 4) {
            float acc = bias;
            #pragma unroll
            for (int p = 0; p < 24; p++) acc += sc[s*24 + p] * w[p];
            pr[s*D + e] = acc;
        }
    }
    __syncthreads();

    // ---------------- transformer layers ----------------
    #pragma unroll 1
    for (int L = 0; L < 3; L++) {
        // ---- K and V (fused weight pass over x) ----
        {
            const float4* wk4 = (const float4*)(Wk + (size_t)L*D*D + e*D);
            const float4* wv4 = (const float4*)(Wv + (size_t)L*D*D + e*D);
            const float bke = bk[L*D + e], bve = bv[L*D + e];
            float ak[8], av[8];
            #pragma unroll
            for (int j = 0; j < 8; j++) { ak[j] = bke; av[j] = bve; }
            #pragma unroll 4
            for (int kk = 0; kk < 32; kk++) {
                float4 a = wk4[kk], b4 = wv4[kk];
                #pragma unroll
                for (int j = 0; j < 8; j++) {
                    int t = pg + 4*j;
                    if (t < PN) {
                        float4 xx = *(const float4*)(xb + t*D + kk*4);
                        ak[j] += xx.x*a.x  + xx.y*a.y  + xx.z*a.z  + xx.w*a.w;
                        av[j] += xx.x*b4.x + xx.y*b4.y + xx.z*b4.z + xx.w*b4.w;
                    }
                }
            }
            #pragma unroll
            for (int j = 0; j < 8; j++) {
                int t = pg + 4*j;
                if (t < PN) { kb[t*D+e] = ak[j]; vb[t*D+e] = av[j]; }
            }
        }
        // ---- Q into scratch ----
        {
            const float4* wq4 = (const float4*)(Wq + (size_t)L*D*D + e*D);
            const float bqe = bq[L*D + e];
            float aq[8];
            #pragma unroll
            for (int j = 0; j < 8; j++) aq[j] = bqe;
            #pragma unroll 4
            for (int kk = 0; kk < 32; kk++) {
                float4 a = wq4[kk];
                #pragma unroll
                for (int j = 0; j < 8; j++) {
                    int t = pg + 4*j;
                    if (t < PN) {
                        float4 xx = *(const float4*)(pr + t*D + kk*4);
                        aq[j] += xx.x*a.x + xx.y*a.y + xx.z*a.z + xx.w*a.w;
                    }
                }
            }
            #pragma unroll
            for (int j = 0; j < 8; j++) {
                int t = pg + 4*j;
                if (t < PN) sc[t*D+e] = aq[j];
            }
        }
        __syncthreads();

        // ---- scores += scale * q.k  (raw accumulation across layers) ----
        for (int idx = tid; idx < NHH*PN*PN; idx += NT) {
            int h = idx / (PN*PN);
            int r = idx % (PN*PN);
            int p = r / PN, t = r % PN;
            const float* qp = sc + p*D + h*8;
            const float* kp = kb + t*D + h*8;
            float a = 0.f;
            #pragma unroll
            for (int j = 0; j < 8; j++) a += qp[j]*kp[j];
            sco[idx] += a * SCALE;
        }
        __syncthreads();

        // ---- softmax (registers only) + attn@V -> o into scratch ----
        if (tid < NHH*PN) {
            int h = tid / PN, p = tid % PN;
            const float* srow = sco + h*PN*PN + p*PN;
            float m = -1e30f;
            #pragma unroll
            for (int t = 0; t < PN; t++) m = fmaxf(m, srow[t]);
            float w[PN]; float ss = 0.f;
            #pragma unroll
            for (int t = 0; t < PN; t++) { w[t] = __expf(srow[t]-m); ss += w[t]; }
            float inv = 1.f/ss;
            #pragma unroll
            for (int j = 0; j < 8; j++) {
                float a = 0.f;
                #pragma unroll
                for (int t = 0; t < PN; t++) a += w[t] * vb[t*D + h*8 + j];
                sc[p*D + h*8 + j] = a * inv;
            }
        }
        __syncthreads();

        // ---- O projection + residual into pred ----
        {
            const float4* wo4 = (const float4*)(Wo + (size_t)L*D*D + e*D);
            const float boe = bo[L*D + e];
            float ao[8];
            #pragma unroll
            for (int j = 0; j < 8; j++) ao[j] = boe;
            #pragma unroll 4
            for (int kk = 0; kk < 32; kk++) {
                float4 a = wo4[kk];
                #pragma unroll
                for (int j = 0; j < 8; j++) {
                    int t = pg + 4*j;
                    if (t < PN) {
                        float4 oo = *(const float4*)(sc + t*D + kk*4);
                        ao[j] += oo.x*a.x + oo.y*a.y + oo.z*a.z + oo.w*a.w;
                    }
                }
            }
            #pragma unroll
            for (int j = 0; j < 8; j++) {
                int t = pg + 4*j;
                if (t < PN) pr[t*D+e] += ao[j];
            }
        }
        __syncthreads();
        ln_rows(pr, g1 + L*D, be1 + L*D);
        __syncthreads();

        // ---- FFN up (a and gate halves fused) -> ag into scratch ----
        {
            const float4* w1a = (const float4*)(W1 + (size_t)L*256*D + e*D);
            const float4* w1g = (const float4*)(W1 + (size_t)L*256*D + (e+128)*D);
            const float ba = b1[L*256 + e], bg = b1[L*256 + 128 + e];
            float aa[8], ag[8];
            #pragma unroll
            for (int j = 0; j < 8; j++) { aa[j] = ba; ag[j] = bg; }
            #pragma unroll 4
            for (int kk = 0; kk < 32; kk++) {
                float4 wa = w1a[kk], wg = w1g[kk];
                #pragma unroll
                for (int j = 0; j < 8; j++) {
                    int t = pg + 4*j;
                    if (t < PN) {
                        float4 pp = *(const float4*)(pr + t*D + kk*4);
                        aa[j] += pp.x*wa.x + pp.y*wa.y + pp.z*wa.z + pp.w*wa.w;
                        ag[j] += pp.x*wg.x + pp.y*wg.y + pp.z*wg.z + pp.w*wg.w;
                    }
                }
            }
            #pragma unroll
            for (int j = 0; j < 8; j++) {
                int t = pg + 4*j;
                if (t < PN) {
                    float gv  = ag[j];
                    float gel = 0.5f * gv * (1.f + erff(gv * 0.70710678118654752f));
                    sc[t*D+e] = aa[j] * gel;
                }
            }
        }
        __syncthreads();

        // ---- FFN down + residual into pred ----
        {
            const float4* w24 = (const float4*)(W2 + (size_t)L*D*D + e*D);
            const float b2e = b2[L*D + e];
            float a2[8];
            #pragma unroll
            for (int j = 0; j < 8; j++) a2[j] = b2e;
            #pragma unroll 4
            for (int kk = 0; kk < 32; kk++) {
                float4 a = w24[kk];
                #pragma unroll
                for (int j = 0; j < 8; j++) {
                    int t = pg + 4*j;
                    if (t < PN) {
                        float4 hh = *(const float4*)(sc + t*D + kk*4);
                        a2[j] += hh.x*a.x + hh.y*a.y + hh.z*a.z + hh.w*a.w;
                    }
                }
            }
            #pragma unroll
            for (int j = 0; j < 8; j++) {
                int t = pg + 4*j;
                if (t < PN) pr[t*D+e] += a2[j];
            }
        }
        __syncthreads();
        ln_rows(pr, g2 + L*D, be2 + L*D);
        __syncthreads();
    }

    // ---------------- output head + de-normalization ----------------
    const float sd = red[34];
    for (int idx = tid; idx < PN*24; idx += NT) {
        int p = idx / 24, pl = idx % 24;
        const float4* pw = (const float4*)(Pw + pl*D);
        const float4* pp = (const float4*)(pr + p*D);
        float acc = Pb[pl];
        #pragma unroll
        for (int kk = 0; kk < 32; kk++) {
            float4 a = pw[kk], x4 = pp[kk];
            acc += x4.x*a.x + x4.y*a.y + x4.z*a.z + x4.w*a.w;
        }
        out[(size_t)blk*SEQ + idx] = acc * sd + mu;
    }
}

extern "C" void kernel_launch(void* const* d_in, const int* in_sizes, int n_in,
                              void* d_out, int out_size)
{
    (void)in_sizes; (void)n_in; (void)out_size;
    cudaFuncSetAttribute(ts_kernel, cudaFuncAttributeMaxDynamicSharedMemorySize, SMEM_BYTES);
    ts_kernel<<<16*CIN, NT, SMEM_BYTES>>>(
        (const float*)d_in[0],  (const float*)d_in[1],  (const float*)d_in[2],
        (const float*)d_in[3],  (const float*)d_in[4],  (const float*)d_in[5],
        (const float*)d_in[6],  (const float*)d_in[7],  (const float*)d_in[8],
        (const float*)d_in[9],  (const float*)d_in[10], (const float*)d_in[11],
        (const float*)d_in[12], (const float*)d_in[13], (const float*)d_in[14],
        (const float*)d_in[15], (const float*)d_in[16], (const float*)d_in[17],
        (const float*)d_in[18], (const float*)d_in[19], (const float*)d_in[20],
        (const float*)d_in[21], (const float*)d_in[22],
        (float*)d_out);
}

// round 4
// speedup vs baseline: 1.2414x; 1.1726x over previous
#include <cuda_runtime.h>
#include <math.h>

#define NT     512
#define PN     30
#define TP     33
#define CIN    321
#define SEQ    720
#define SCALEF 0.35355339059327373f   // 8^-0.5

typedef unsigned long long ull;

// ---------- packed f32x2 helpers ----------
__device__ __forceinline__ ull pk(float lo, float hi) {
    ull r; asm("mov.b64 %0, {%1, %2};" : "=l"(r) : "f"(lo), "f"(hi)); return r;
}
__device__ __forceinline__ float fin(ull a) {
    float x, y; asm("mov.b64 {%0, %1}, %2;" : "=f"(x), "=f"(y) : "l"(a)); return x + y;
}
__device__ __forceinline__ ull ffma2(ull a, ull b, ull c) {
    ull d; asm("fma.rn.f32x2 %0, %1, %2, %3;" : "=l"(d) : "l"(a), "l"(b), "l"(c)); return d;
}
__device__ __forceinline__ void ldg2(const float* p, ull& a, ull& b) {
    asm("ld.global.nc.v2.u64 {%0, %1}, [%2];" : "=l"(a), "=l"(b) : "l"(p));
}

// ---------- smem layout (floats) ----------
#define OFF_XT   0          // x   [128][33]
#define OFF_PRT  4224       // pred[128][33]
#define OFF_KT   8448       // K   [128][33]   (aliases peT during embed)
#define OFF_VT   12672      // V   [128][33]
#define OFF_SCR  16896      // scratch [128][33]: znT/dummies -> q -> o -> ffn act
#define OFF_SCO  21120      // scores [16][30][30] (aliases outb at head)
#define OFF_RED  35520      // 1152 reduction floats
#define SMEM_FLOATS 36672
#define SMEM_BYTES  (SMEM_FLOATS * 4)

// warp computes 8 output features (rows of W, K=128), lane = token.
__device__ __forceinline__ void accum8(const float* __restrict__ actT,
                                       const float* __restrict__ w0,
                                       int lane, ull acc[8]) {
    #pragma unroll
    for (int j = 0; j < 8; j++) acc[j] = 0ULL;
    #pragma unroll 2
    for (int c = 0; c < 8; c++) {
        ull ap[8];
        #pragma unroll
        for (int j = 0; j < 8; j++)
            ap[j] = pk(actT[(c*16 + 2*j)*TP + lane], actT[(c*16 + 2*j + 1)*TP + lane]);
        #pragma unroll
        for (int f = 0; f < 8; f++) {
            const float* wr = w0 + f*128 + c*16;
            #pragma unroll
            for (int q = 0; q < 4; q++) {
                ull wa, wb; ldg2(wr + 4*q, wa, wb);
                acc[f] = ffma2(ap[2*q],     wa, acc[f]);
                acc[f] = ffma2(ap[2*q + 1], wb, acc[f]);
            }
        }
    }
}

// dual: two weight bases share the activation chunks
__device__ __forceinline__ void accum8d(const float* __restrict__ actT,
                                        const float* __restrict__ wA,
                                        const float* __restrict__ wB,
                                        int lane, ull aA[8], ull aB[8]) {
    #pragma unroll
    for (int j = 0; j < 8; j++) { aA[j] = 0ULL; aB[j] = 0ULL; }
    #pragma unroll 2
    for (int c = 0; c < 8; c++) {
        ull ap[8];
        #pragma unroll
        for (int j = 0; j < 8; j++)
            ap[j] = pk(actT[(c*16 + 2*j)*TP + lane], actT[(c*16 + 2*j + 1)*TP + lane]);
        #pragma unroll
        for (int f = 0; f < 8; f++) {
            const float* wra = wA + f*128 + c*16;
            const float* wrb = wB + f*128 + c*16;
            #pragma unroll
            for (int q = 0; q < 4; q++) {
                ull wa, wb; ldg2(wra + 4*q, wa, wb);
                aA[f] = ffma2(ap[2*q],     wa, aA[f]);
                aA[f] = ffma2(ap[2*q + 1], wb, aA[f]);
                ull va, vb; ldg2(wrb + 4*q, va, vb);
                aB[f] = ffma2(ap[2*q],     va, aB[f]);
                aB[f] = ffma2(ap[2*q + 1], vb, aB[f]);
            }
        }
    }
}

// patch version: K = 24
__device__ __forceinline__ void accum8p(const float* __restrict__ actT,
                                        const float* __restrict__ w0,
                                        int lane, ull acc[8]) {
    ull ap[12];
    #pragma unroll
    for (int j = 0; j < 12; j++)
        ap[j] = pk(actT[(2*j)*TP + lane], actT[(2*j + 1)*TP + lane]);
    #pragma unroll
    for (int f = 0; f < 8; f++) {
        const float* wr = w0 + f*24;
        acc[f] = 0ULL;
        #pragma unroll
        for (int q = 0; q < 6; q++) {
            ull wa, wb; ldg2(wr + 4*q, wa, wb);
            acc[f] = ffma2(ap[2*q],     wa, acc[f]);
            acc[f] = ffma2(ap[2*q + 1], wb, acc[f]);
        }
    }
}

// transposed layernorm over bufT [128][TP] (tokens in lanes); 2 internal syncs
__device__ __forceinline__ void ln_T(float* bufT, const float* __restrict__ g,
                                     const float* __restrict__ be, float* red) {
    const int tid = threadIdx.x;
    const int t   = tid & 31;
    const int rep = tid >> 5;
    float v[8]; float s = 0.f, q = 0.f;
    #pragma unroll
    for (int j = 0; j < 8; j++) {
        v[j] = bufT[(rep*8 + j)*TP + t];
        s += v[j]; q += v[j]*v[j];
    }
    red[rep*32 + t] = s; red[512 + rep*32 + t] = q;
    __syncthreads();
    if (tid < 32) {
        float S = 0.f, Q = 0.f;
        #pragma unroll
        for (int r2 = 0; r2 < 16; r2++) { S += red[r2*32 + tid]; Q += red[512 + r2*32 + tid]; }
        float m = S * (1.f/128.f);
        float var = Q * (1.f/128.f) - m*m;
        red[1024 + tid] = m;
        red[1056 + tid] = rsqrtf(var + 1e-5f);
    }
    __syncthreads();
    const float m = red[1024 + t], rr = red[1056 + t];
    #pragma unroll
    for (int j = 0; j < 8; j++) {
        int d = rep*8 + j;
        bufT[d*TP + t] = (v[j] - m)*rr*g[d] + be[d];
    }
}

__global__ __launch_bounds__(NT, 1)
void ts_kernel(const float* __restrict__ z,
               const float* __restrict__ WPw, const float* __restrict__ WPb,
               const float* __restrict__ PE,  const float* __restrict__ dummies,
               const float* __restrict__ Wq,  const float* __restrict__ bq,
               const float* __restrict__ Wk,  const float* __restrict__ bk,
               const float* __restrict__ Wv,  const float* __restrict__ bv,
               const float* __restrict__ Wo,  const float* __restrict__ bo,
               const float* __restrict__ g1,  const float* __restrict__ be1,
               const float* __restrict__ W1,  const float* __restrict__ b1,
               const float* __restrict__ W2,  const float* __restrict__ b2,
               const float* __restrict__ g2,  const float* __restrict__ be2,
               const float* __restrict__ Pw,  const float* __restrict__ Pb,
               float* __restrict__ out)
{
    extern __shared__ float sm[];
    float* xT  = sm + OFF_XT;
    float* prT = sm + OFF_PRT;
    float* kT  = sm + OFF_KT;
    float* vT  = sm + OFF_VT;
    float* scr = sm + OFF_SCR;
    float* sco = sm + OFF_SCO;
    float* red = sm + OFF_RED;

    const int tid  = threadIdx.x;
    const int wid  = tid >> 5;
    const int lane = tid & 31;
    const int f0   = wid * 8;
    const int blk  = blockIdx.x;
    const int ch   = blk % CIN;
    const float* zr = z + (size_t)blk * SEQ;

    // -------- instance stats over SEQ --------
    float s1 = 0.f, s2 = 0.f;
    for (int i = tid; i < SEQ; i += NT) { float v = zr[i]; s1 += v; s2 += v*v; }
    #pragma unroll
    for (int o = 16; o; o >>= 1) {
        s1 += __shfl_xor_sync(0xffffffffu, s1, o);
        s2 += __shfl_xor_sync(0xffffffffu, s2, o);
    }
    if (lane == 0) { red[wid] = s1; red[16 + wid] = s2; }
    __syncthreads();
    if (tid == 0) {
        float S1 = 0.f, S2 = 0.f;
        #pragma unroll
        for (int w = 0; w < 16; w++) { S1 += red[w]; S2 += red[16 + w]; }
        float mu  = S1 / (float)SEQ;
        float var = S2 / (float)SEQ - mu*mu;
        float sd  = sqrtf(var + 1e-5f);
        red[1100] = mu; red[1101] = 1.f/sd; red[1102] = sd;
    }
    __syncthreads();
    const float mu = red[1100], rstd = red[1101];

    // -------- stage znT (scratch), peT (kT alias); zero scores --------
    for (int i = tid; i < SEQ; i += NT) {
        int s = i / 24, p = i - s*24;
        scr[p*TP + s] = (zr[i] - mu) * rstd;
    }
    for (int i = tid; i < PN*128; i += NT) {
        kT[(i & 127)*TP + (i >> 7)] = PE[i];        // peT
    }
    for (int i = tid; i < 16*PN*PN; i += NT) sco[i] = 0.f;
    __syncthreads();

    // -------- patch embedding: x (with PE), then pred from dummies --------
    {
        ull acc[8];
        accum8p(scr, WPw + f0*24, lane, acc);
        if (lane < PN) {
            #pragma unroll
            for (int j = 0; j < 8; j++)
                xT[(f0+j)*TP + lane] = fin(acc[j]) + WPb[f0+j] + kT[(f0+j)*TP + lane];
        }
    }
    __syncthreads();
    {
        const float* dm = dummies + (size_t)ch * PN * 24;
        for (int i = tid; i < PN*24; i += NT) {
            int s = i / 24, p = i - s*24;
            scr[p*TP + s] = dm[i];
        }
    }
    __syncthreads();
    {
        ull acc[8];
        accum8p(scr, WPw + f0*24, lane, acc);
        if (lane < PN) {
            #pragma unroll
            for (int j = 0; j < 8; j++)
                prT[(f0+j)*TP + lane] = fin(acc[j]) + WPb[f0+j];
        }
    }
    __syncthreads();

    // -------- transformer layers --------
    #pragma unroll 1
    for (int L = 0; L < 3; L++) {
        const size_t o128 = (size_t)L * 16384;

        // K,V (fused) from x; Q from pred -> scr
        {
            ull ak[8], av[8];
            accum8d(xT, Wk + o128 + f0*128, Wv + o128 + f0*128, lane, ak, av);
            if (lane < PN) {
                #pragma unroll
                for (int j = 0; j < 8; j++) {
                    kT[(f0+j)*TP + lane] = fin(ak[j]) + bk[L*128 + f0 + j];
                    vT[(f0+j)*TP + lane] = fin(av[j]) + bv[L*128 + f0 + j];
                }
            }
            ull aq[8];
            accum8(prT, Wq + o128 + f0*128, lane, aq);
            if (lane < PN) {
                #pragma unroll
                for (int j = 0; j < 8; j++)
                    scr[(f0+j)*TP + lane] = fin(aq[j]) + bq[L*128 + f0 + j];
            }
        }
        __syncthreads();

        // attention: warp owns (h,p) rows; no internal syncs needed
        {
            const int t = lane;
            for (int r = wid; r < 16*PN; r += 16) {
                const int h = r / PN, p = r - h*PN;
                float qv[8], kv[8];
                #pragma unroll
                for (int j = 0; j < 8; j++) {
                    qv[j] = scr[(h*8+j)*TP + p];      // broadcast
                    kv[j] = kT [(h*8+j)*TP + t];
                }
                float s = 0.f;
                #pragma unroll
                for (int j = 0; j < 8; j++) s += qv[j]*kv[j];
                float* sp = sco + r*PN;
                float sv = -1e30f;
                if (t < PN) { sv = sp[t] + s*SCALEF; sp[t] = sv; }
                float m = sv;
                #pragma unroll
                for (int o = 16; o; o >>= 1) m = fmaxf(m, __shfl_xor_sync(0xffffffffu, m, o));
                float w = (t < PN) ? __expf(sv - m) : 0.f;
                float ssum = w;
                #pragma unroll
                for (int o = 16; o; o >>= 1) ssum += __shfl_xor_sync(0xffffffffu, ssum, o);
                const float inv = 1.f / ssum;
                float ov[8];
                #pragma unroll
                for (int j = 0; j < 8; j++) {
                    float vv = (t < PN) ? vT[(h*8+j)*TP + t] : 0.f;
                    float a = w * vv;
                    #pragma unroll
                    for (int o = 16; o; o >>= 1) a += __shfl_xor_sync(0xffffffffu, a, o);
                    ov[j] = a;
                }
                if (t == 0) {
                    #pragma unroll
                    for (int j = 0; j < 8; j++)
                        scr[(h*8+j)*TP + p] = ov[j] * inv;   // overwrites own q elems
                }
            }
        }
        __syncthreads();

        // O projection + residual
        {
            ull ao[8];
            accum8(scr, Wo + o128 + f0*128, lane, ao);
            if (lane < PN) {
                #pragma unroll
                for (int j = 0; j < 8; j++)
                    prT[(f0+j)*TP + lane] += fin(ao[j]) + bo[L*128 + f0 + j];
            }
        }
        __syncthreads();
        ln_T(prT, g1 + L*128, be1 + L*128, red);
        __syncthreads();

        // FFN up (a + gate fused) -> gated product into scr
        {
            const float* w1b = W1 + (size_t)L*32768;
            ull aa[8], ag[8];
            accum8d(prT, w1b + f0*128, w1b + (f0+128)*128, lane, aa, ag);
            if (lane < PN) {
                #pragma unroll
                for (int j = 0; j < 8; j++) {
                    float a  = fin(aa[j]) + b1[L*256 + f0 + j];
                    float gv = fin(ag[j]) + b1[L*256 + 128 + f0 + j];
                    float gel = 0.5f * gv * (1.f + erff(gv * 0.70710678118654752f));
                    scr[(f0+j)*TP + lane] = a * gel;
                }
            }
        }
        __syncthreads();

        // FFN down + residual
        {
            ull a2[8];
            accum8(scr, W2 + o128 + f0*128, lane, a2);
            if (lane < PN) {
                #pragma unroll
                for (int j = 0; j < 8; j++)
                    prT[(f0+j)*TP + lane] += fin(a2[j]) + b2[L*128 + f0 + j];
            }
        }
        __syncthreads();
        ln_T(prT, g2 + L*128, be2 + L*128, red);
        __syncthreads();
    }

    // -------- output head: warps 0..11 handle 2 patch-lanes each --------
    float* outb = sco;   // 720 floats, scores dead now
    if (wid < 12) {
        const int pl0 = wid * 2;
        ull a0 = 0ULL, a1 = 0ULL;
        #pragma unroll 2
        for (int c = 0; c < 8; c++) {
            ull ap[8];
            #pragma unroll
            for (int j = 0; j < 8; j++)
                ap[j] = pk(prT[(c*16 + 2*j)*TP + lane], prT[(c*16 + 2*j + 1)*TP + lane]);
            const float* wr0 = Pw + pl0*128 + c*16;
            const float* wr1 = Pw + (pl0+1)*128 + c*16;
            #pragma unroll
            for (int q = 0; q < 4; q++) {
                ull wa, wb; ldg2(wr0 + 4*q, wa, wb);
                a0 = ffma2(ap[2*q], wa, a0);
                a0 = ffma2(ap[2*q+1], wb, a0);
                ull va, vb; ldg2(wr1 + 4*q, va, vb);
                a1 = ffma2(ap[2*q], va, a1);
                a1 = ffma2(ap[2*q+1], vb, a1);
            }
        }
        if (lane < PN) {
            outb[lane*24 + pl0]     = fin(a0) + Pb[pl0];
            outb[lane*24 + pl0 + 1] = fin(a1) + Pb[pl0 + 1];
        }
    }
    __syncthreads();
    const float sd = red[1102];
    for (int i = tid; i < SEQ; i += NT)
        out[(size_t)blk*SEQ + i] = outb[i]*sd + mu;
}

extern "C" void kernel_launch(void* const* d_in, const int* in_sizes, int n_in,
                              void* d_out, int out_size)
{
    (void)in_sizes; (void)n_in; (void)out_size;
    cudaFuncSetAttribute(ts_kernel, cudaFuncAttributeMaxDynamicSharedMemorySize, SMEM_BYTES);
    ts_kernel<<<16*CIN, NT, SMEM_BYTES>>>(
        (const float*)d_in[0],  (const float*)d_in[1],  (const float*)d_in[2],
        (const float*)d_in[3],  (const float*)d_in[4],  (const float*)d_in[5],
        (const float*)d_in[6],  (const float*)d_in[7],  (const float*)d_in[8],
        (const float*)d_in[9],  (const float*)d_in[10], (const float*)d_in[11],
        (const float*)d_in[12], (const float*)d_in[13], (const float*)d_in[14],
        (const float*)d_in[15], (const float*)d_in[16], (const float*)d_in[17],
        (const float*)d_in[18], (const float*)d_in[19], (const float*)d_in[20],
        (const float*)d_in[21], (const float*)d_in[22],
        (float*)d_out);
}

// round 6
// speedup vs baseline: 1.7755x; 1.4303x over previous
#include <cuda_runtime.h>
#include <cstdint>
#include <math.h>

#define NT     512
#define PN     30
#define TP     33
#define CIN    321
#define SEQ    720
#define SCALEF 0.35355339059327373f   // 8^-0.5

typedef unsigned long long ull;

// ---------- packed f32x2 helpers ----------
__device__ __forceinline__ ull pk(float lo, float hi) {
    ull r; asm("mov.b64 %0, {%1, %2};" : "=l"(r) : "f"(lo), "f"(hi)); return r;
}
__device__ __forceinline__ float fin(ull a) {
    float x, y; asm("mov.b64 {%0, %1}, %2;" : "=f"(x), "=f"(y) : "l"(a)); return x + y;
}
__device__ __forceinline__ ull ffma2(ull a, ull b, ull c) {
    ull d; asm("fma.rn.f32x2 %0, %1, %2, %3;" : "=l"(d) : "l"(a), "l"(b), "l"(c)); return d;
}
__device__ __forceinline__ void ldg2(const float* p, ull& a, ull& b) {
    asm("ld.global.nc.v2.u64 {%0, %1}, [%2];" : "=l"(a), "=l"(b) : "l"(p));
}
__device__ __forceinline__ void lds2(uint32_t a32, ull& a, ull& b) {
    asm("ld.shared.v2.u64 {%0, %1}, [%2];" : "=l"(a), "=l"(b) : "r"(a32));
}

// ---------- smem layout (floats) ----------
#define OFF_XT   0          // x   [128][33]
#define OFF_PRT  4224       // pred[128][33]
#define OFF_KT   8448       // K   [128][33]   (aliases peT during embed)
#define OFF_VT   12672      // V   [128][33]
#define OFF_SCR  16896      // scratch [128][33]
#define OFF_SCO  21120      // scores [16][30][30] (aliases outb at head)
#define OFF_RED  35520      // 1152 reduction floats
#define OFF_W    36672      // weight staging: 16 warps x 4KB = 64KB
#define SMEM_FLOATS (36672 + 16384)
#define SMEM_BYTES  (SMEM_FLOATS * 4)

// ---------- async weight staging: warp-private 4KB slot (8 rows x 128 f) ----------
__device__ __forceinline__ void fill_issue(uint32_t wslot, const float* __restrict__ Wg,
                                           int f0, int lane) {
    uint32_t dst = wslot + lane*16;
    const float* src = Wg + f0*128 + lane*4;
    #pragma unroll
    for (int i = 0; i < 8; i++)
        asm volatile("cp.async.cg.shared.global [%0], [%1], 16;"
                     :: "r"(dst + i*512u), "l"(src + (size_t)i*128) : "memory");
    asm volatile("cp.async.commit_group;" ::: "memory");
}
__device__ __forceinline__ void fill_wait() {
    asm volatile("cp.async.wait_group 0;" ::: "memory");
    __syncwarp();
}

// warp computes 8 output features from its smem weight slot; lane = token.
__device__ __forceinline__ void accum8s(const float* __restrict__ actT,
                                        uint32_t wslot, int lane, ull acc[8]) {
    #pragma unroll
    for (int j = 0; j < 8; j++) acc[j] = 0ULL;
    #pragma unroll 2
    for (int c = 0; c < 8; c++) {
        ull ap[8];
        #pragma unroll
        for (int j = 0; j < 8; j++)
            ap[j] = pk(actT[(c*16 + 2*j)*TP + lane], actT[(c*16 + 2*j + 1)*TP + lane]);
        #pragma unroll
        for (int f = 0; f < 8; f++) {
            uint32_t wr = wslot + f*512 + c*64;
            #pragma unroll
            for (int q = 0; q < 2; q++) {
                ull wa, wb, wc, wd;
                lds2(wr + q*32,      wa, wb);
                lds2(wr + q*32 + 16, wc, wd);
                acc[f] = ffma2(ap[4*q],   wa, acc[f]);
                acc[f] = ffma2(ap[4*q+1], wb, acc[f]);
                acc[f] = ffma2(ap[4*q+2], wc, acc[f]);
                acc[f] = ffma2(ap[4*q+3], wd, acc[f]);
            }
        }
    }
}

// patch embedding: K = 24, weights via LDG (tiny)
__device__ __forceinline__ void accum8p(const float* __restrict__ actT,
                                        const float* __restrict__ w0,
                                        int lane, ull acc[8]) {
    ull ap[12];
    #pragma unroll
    for (int j = 0; j < 12; j++)
        ap[j] = pk(actT[(2*j)*TP + lane], actT[(2*j + 1)*TP + lane]);
    #pragma unroll
    for (int f = 0; f < 8; f++) {
        const float* wr = w0 + f*24;
        acc[f] = 0ULL;
        #pragma unroll
        for (int q = 0; q < 6; q++) {
            ull wa, wb; ldg2(wr + 4*q, wa, wb);
            acc[f] = ffma2(ap[2*q],     wa, acc[f]);
            acc[f] = ffma2(ap[2*q + 1], wb, acc[f]);
        }
    }
}

// transposed layernorm over bufT [128][TP] (tokens in lanes); 2 internal syncs
__device__ __forceinline__ void ln_T(float* bufT, const float* __restrict__ g,
                                     const float* __restrict__ be, float* red) {
    const int tid = threadIdx.x;
    const int t   = tid & 31;
    const int rep = tid >> 5;
    float v[8]; float s = 0.f, q = 0.f;
    #pragma unroll
    for (int j = 0; j < 8; j++) {
        v[j] = bufT[(rep*8 + j)*TP + t];
        s += v[j]; q += v[j]*v[j];
    }
    red[rep*32 + t] = s; red[512 + rep*32 + t] = q;
    __syncthreads();
    if (tid < 32) {
        float S = 0.f, Q = 0.f;
        #pragma unroll
        for (int r2 = 0; r2 < 16; r2++) { S += red[r2*32 + tid]; Q += red[512 + r2*32 + tid]; }
        float m = S * (1.f/128.f);
        float var = Q * (1.f/128.f) - m*m;
        red[1024 + tid] = m;
        red[1056 + tid] = rsqrtf(var + 1e-5f);
    }
    __syncthreads();
    const float m = red[1024 + t], rr = red[1056 + t];
    #pragma unroll
    for (int j = 0; j < 8; j++) {
        int d = rep*8 + j;
        bufT[d*TP + t] = (v[j] - m)*rr*g[d] + be[d];
    }
}

__global__ __launch_bounds__(NT, 1)
void ts_kernel(const float* __restrict__ z,
               const float* __restrict__ WPw, const float* __restrict__ WPb,
               const float* __restrict__ PE,  const float* __restrict__ dummies,
               const float* __restrict__ Wq,  const float* __restrict__ bq,
               const float* __restrict__ Wk,  const float* __restrict__ bk,
               const float* __restrict__ Wv,  const float* __restrict__ bv,
               const float* __restrict__ Wo,  const float* __restrict__ bo,
               const float* __restrict__ g1,  const float* __restrict__ be1,
               const float* __restrict__ W1,  const float* __restrict__ b1,
               const float* __restrict__ W2,  const float* __restrict__ b2,
               const float* __restrict__ g2,  const float* __restrict__ be2,
               const float* __restrict__ Pw,  const float* __restrict__ Pb,
               float* __restrict__ out)
{
    extern __shared__ float sm[];
    float* xT  = sm + OFF_XT;
    float* prT = sm + OFF_PRT;
    float* kT  = sm + OFF_KT;
    float* vT  = sm + OFF_VT;
    float* scr = sm + OFF_SCR;
    float* sco = sm + OFF_SCO;
    float* red = sm + OFF_RED;

    const int tid  = threadIdx.x;
    const int wid  = tid >> 5;
    const int lane = tid & 31;
    const int f0   = wid * 8;
    const int blk  = blockIdx.x;
    const int ch   = blk % CIN;
    const float* zr = z + (size_t)blk * SEQ;

    const uint32_t wslot =
        (uint32_t)__cvta_generic_to_shared(sm + OFF_W) + (uint32_t)wid * 4096u;

    // prefetch layer-0 Wk while we do stats/embedding
    fill_issue(wslot, Wk, f0, lane);

    // -------- instance stats over SEQ --------
    float s1 = 0.f, s2 = 0.f;
    for (int i = tid; i < SEQ; i += NT) { float v = zr[i]; s1 += v; s2 += v*v; }
    #pragma unroll
    for (int o = 16; o; o >>= 1) {
        s1 += __shfl_xor_sync(0xffffffffu, s1, o);
        s2 += __shfl_xor_sync(0xffffffffu, s2, o);
    }
    if (lane == 0) { red[wid] = s1; red[16 + wid] = s2; }
    __syncthreads();
    if (tid == 0) {
        float S1 = 0.f, S2 = 0.f;
        #pragma unroll
        for (int w = 0; w < 16; w++) { S1 += red[w]; S2 += red[16 + w]; }
        float mu  = S1 / (float)SEQ;
        float var = S2 / (float)SEQ - mu*mu;
        float sd  = sqrtf(var + 1e-5f);
        red[1100] = mu; red[1101] = 1.f/sd; red[1102] = sd;
    }
    __syncthreads();
    const float mu = red[1100], rstd = red[1101];

    // -------- stage znT (scratch), peT (kT alias); zero scores --------
    for (int i = tid; i < SEQ; i += NT) {
        int s = i / 24, p = i - s*24;
        scr[p*TP + s] = (zr[i] - mu) * rstd;
    }
    for (int i = tid; i < PN*128; i += NT) {
        kT[(i & 127)*TP + (i >> 7)] = PE[i];        // peT
    }
    for (int i = tid; i < 16*PN*PN; i += NT) sco[i] = 0.f;
    __syncthreads();

    // -------- patch embedding: x (with PE), then pred from dummies --------
    {
        ull acc[8];
        accum8p(scr, WPw + f0*24, lane, acc);
        if (lane < PN) {
            #pragma unroll
            for (int j = 0; j < 8; j++)
                xT[(f0+j)*TP + lane] = fin(acc[j]) + WPb[f0+j] + kT[(f0+j)*TP + lane];
        }
    }
    __syncthreads();
    {
        const float* dm = dummies + (size_t)ch * PN * 24;
        for (int i = tid; i < PN*24; i += NT) {
            int s = i / 24, p = i - s*24;
            scr[p*TP + s] = dm[i];
        }
    }
    __syncthreads();
    {
        ull acc[8];
        accum8p(scr, WPw + f0*24, lane, acc);
        if (lane < PN) {
            #pragma unroll
            for (int j = 0; j < 8; j++)
                prT[(f0+j)*TP + lane] = fin(acc[j]) + WPb[f0+j];
        }
    }
    __syncthreads();

    // -------- transformer layers --------
    #pragma unroll 1
    for (int L = 0; L < 3; L++) {
        const size_t o128 = (size_t)L * 16384;

        // ---- K pass ----
        {
            fill_wait();
            ull ak[8];
            accum8s(xT, wslot, lane, ak);
            fill_issue(wslot, Wv + o128, f0, lane);
            if (lane < PN) {
                #pragma unroll
                for (int j = 0; j < 8; j++)
                    kT[(f0+j)*TP + lane] = fin(ak[j]) + bk[L*128 + f0 + j];
            }
        }
        // ---- V pass ----
        {
            fill_wait();
            ull av[8];
            accum8s(xT, wslot, lane, av);
            fill_issue(wslot, Wq + o128, f0, lane);
            if (lane < PN) {
                #pragma unroll
                for (int j = 0; j < 8; j++)
                    vT[(f0+j)*TP + lane] = fin(av[j]) + bv[L*128 + f0 + j];
            }
        }
        // ---- Q pass -> scr ----
        {
            fill_wait();
            ull aq[8];
            accum8s(prT, wslot, lane, aq);
            fill_issue(wslot, Wo + o128, f0, lane);
            if (lane < PN) {
                #pragma unroll
                for (int j = 0; j < 8; j++)
                    scr[(f0+j)*TP + lane] = fin(aq[j]) + bq[L*128 + f0 + j];
            }
        }
        __syncthreads();

        // ---- attention: warp owns (h,p) rows ----
        {
            const int t = lane;
            for (int r = wid; r < 16*PN; r += 16) {
                const int h = r / PN, p = r - h*PN;
                float qv[8], kv[8];
                #pragma unroll
                for (int j = 0; j < 8; j++) {
                    qv[j] = scr[(h*8+j)*TP + p];      // broadcast
                    kv[j] = kT [(h*8+j)*TP + t];
                }
                float s = 0.f;
                #pragma unroll
                for (int j = 0; j < 8; j++) s += qv[j]*kv[j];
                float* sp = sco + r*PN;
                float sv = -1e30f;
                if (t < PN) { sv = sp[t] + s*SCALEF; sp[t] = sv; }
                float m = sv;
                #pragma unroll
                for (int o = 16; o; o >>= 1) m = fmaxf(m, __shfl_xor_sync(0xffffffffu, m, o));
                float w = (t < PN) ? __expf(sv - m) : 0.f;
                float ssum = w;
                #pragma unroll
                for (int o = 16; o; o >>= 1) ssum += __shfl_xor_sync(0xffffffffu, ssum, o);
                const float inv = 1.f / ssum;
                float ov[8];
                #pragma unroll
                for (int j = 0; j < 8; j++) {
                    float vv = (t < PN) ? vT[(h*8+j)*TP + t] : 0.f;
                    float a = w * vv;
                    #pragma unroll
                    for (int o = 16; o; o >>= 1) a += __shfl_xor_sync(0xffffffffu, a, o);
                    ov[j] = a;
                }
                if (t == 0) {
                    #pragma unroll
                    for (int j = 0; j < 8; j++)
                        scr[(h*8+j)*TP + p] = ov[j] * inv;
                }
            }
        }
        __syncthreads();

        // ---- O pass + residual ----
        {
            fill_wait();
            ull ao[8];
            accum8s(scr, wslot, lane, ao);
            fill_issue(wslot, W1 + (size_t)L*32768, f0, lane);   // W1 a-half
            if (lane < PN) {
                #pragma unroll
                for (int j = 0; j < 8; j++)
                    prT[(f0+j)*TP + lane] += fin(ao[j]) + bo[L*128 + f0 + j];
            }
        }
        __syncthreads();
        ln_T(prT, g1 + L*128, be1 + L*128, red);
        __syncthreads();

        // ---- FFN up: a-half, then gate-half, gelu combine -> scr ----
        {
            fill_wait();
            ull aa[8];
            accum8s(prT, wslot, lane, aa);
            fill_issue(wslot, W1 + (size_t)L*32768 + 16384, f0, lane);  // gate half
            fill_wait();
            ull ag[8];
            accum8s(prT, wslot, lane, ag);
            fill_issue(wslot, W2 + o128, f0, lane);
            if (lane < PN) {
                #pragma unroll
                for (int j = 0; j < 8; j++) {
                    float a  = fin(aa[j]) + b1[L*256 + f0 + j];
                    float gv = fin(ag[j]) + b1[L*256 + 128 + f0 + j];
                    float gel = 0.5f * gv * (1.f + erff(gv * 0.70710678118654752f));
                    scr[(f0+j)*TP + lane] = a * gel;
                }
            }
        }
        __syncthreads();

        // ---- FFN down + residual ----
        {
            fill_wait();
            ull a2[8];
            accum8s(scr, wslot, lane, a2);
            if (L < 2) fill_issue(wslot, Wk + (size_t)(L+1)*16384, f0, lane);
            if (lane < PN) {
                #pragma unroll
                for (int j = 0; j < 8; j++)
                    prT[(f0+j)*TP + lane] += fin(a2[j]) + b2[L*128 + f0 + j];
            }
        }
        __syncthreads();
        ln_T(prT, g2 + L*128, be2 + L*128, red);
        __syncthreads();
    }

    // -------- output head: warps 0..11 handle 2 patch-lanes each --------
    float* outb = sco;   // 720 floats, scores dead now
    if (wid < 12) {
        const int pl0 = wid * 2;
        ull a0 = 0ULL, a1 = 0ULL;
        #pragma unroll 2
        for (int c = 0; c < 8; c++) {
            ull ap[8];
            #pragma unroll
            for (int j = 0; j < 8; j++)
                ap[j] = pk(prT[(c*16 + 2*j)*TP + lane], prT[(c*16 + 2*j + 1)*TP + lane]);
            const float* wr0 = Pw + pl0*128 + c*16;
            const float* wr1 = Pw + (pl0+1)*128 + c*16;
            #pragma unroll
            for (int q = 0; q < 4; q++) {
                ull wa, wb; ldg2(wr0 + 4*q, wa, wb);
                a0 = ffma2(ap[2*q], wa, a0);
                a0 = ffma2(ap[2*q+1], wb, a0);
                ull va, vb; ldg2(wr1 + 4*q, va, vb);
                a1 = ffma2(ap[2*q], va, a1);
                a1 = ffma2(ap[2*q+1], vb, a1);
            }
        }
        if (lane < PN) {
            outb[lane*24 + pl0]     = fin(a0) + Pb[pl0];
            outb[lane*24 + pl0 + 1] = fin(a1) + Pb[pl0 + 1];
        }
    }
    __syncthreads();
    const float sd = red[1102];
    for (int i = tid; i < SEQ; i += NT)
        out[(size_t)blk*SEQ + i] = outb[i]*sd + mu;
}

extern "C" void kernel_launch(void* const* d_in, const int* in_sizes, int n_in,
                              void* d_out, int out_size)
{
    (void)in_sizes; (void)n_in; (void)out_size;
    cudaFuncSetAttribute(ts_kernel, cudaFuncAttributeMaxDynamicSharedMemorySize, SMEM_BYTES);
    ts_kernel<<<16*CIN, NT, SMEM_BYTES>>>(
        (const float*)d_in[0],  (const float*)d_in[1],  (const float*)d_in[2],
        (const float*)d_in[3],  (const float*)d_in[4],  (const float*)d_in[5],
        (const float*)d_in[6],  (const float*)d_in[7],  (const float*)d_in[8],
        (const float*)d_in[9],  (const float*)d_in[10], (const float*)d_in[11],
        (const float*)d_in[12], (const float*)d_in[13], (const float*)d_in[14],
        (const float*)d_in[15], (const float*)d_in[16], (const float*)d_in[17],
        (const float*)d_in[18], (const float*)d_in[19], (const float*)d_in[20],
        (const float*)d_in[21], (const float*)d_in[22],
        (float*)d_out);
}

// round 7
// speedup vs baseline: 1.7763x; 1.0004x over previous
#include <cuda_runtime.h>
#include <cstdint>
#include <math.h>

#define NT     512
#define PN     30
#define TP     33
#define CIN    321
#define SEQ    720
#define SCALEF 0.35355339059327373f   // 8^-0.5

typedef unsigned long long ull;

// ---------- packed f32x2 helpers ----------
__device__ __forceinline__ ull pk(float lo, float hi) {
    ull r; asm("mov.b64 %0, {%1, %2};" : "=l"(r) : "f"(lo), "f"(hi)); return r;
}
__device__ __forceinline__ float fin(ull a) {
    float x, y; asm("mov.b64 {%0, %1}, %2;" : "=f"(x), "=f"(y) : "l"(a)); return x + y;
}
__device__ __forceinline__ ull ffma2(ull a, ull b, ull c) {
    ull d; asm("fma.rn.f32x2 %0, %1, %2, %3;" : "=l"(d) : "l"(a), "l"(b), "l"(c)); return d;
}
__device__ __forceinline__ void ldg2(const float* p, ull& a, ull& b) {
    asm("ld.global.nc.v2.u64 {%0, %1}, [%2];" : "=l"(a), "=l"(b) : "l"(p));
}
__device__ __forceinline__ void lds2(uint32_t a32, ull& a, ull& b) {
    asm("ld.shared.v2.u64 {%0, %1}, [%2];" : "=l"(a), "=l"(b) : "r"(a32));
}

// ---------- smem layout (floats) ----------
#define OFF_XT   0          // x   [128][33]
#define OFF_PRT  4224       // pred[128][33]
#define OFF_KT   8448       // K   [128][33]   (aliases peT during embed)
#define OFF_VT   12672      // V   [128][33]
#define OFF_SCR  16896      // scratch [128][33]
#define OFF_SCO  21120      // scores [16][30][30] (aliases outb at head)
#define OFF_RED  35520      // 1152 reduction floats
#define OFF_W    36672      // weight staging: 16 warps x 4KB = 64KB
#define SMEM_FLOATS (36672 + 16384)
#define SMEM_BYTES  (SMEM_FLOATS * 4)

// ---------- async weight staging: warp-private 4KB slot (8 rows x 128 f) ----------
__device__ __forceinline__ void fill_issue(uint32_t wslot, const float* __restrict__ Wg,
                                           int f0, int lane) {
    uint32_t dst = wslot + lane*16;
    const float* src = Wg + f0*128 + lane*4;
    #pragma unroll
    for (int i = 0; i < 8; i++)
        asm volatile("cp.async.cg.shared.global [%0], [%1], 16;"
                     :: "r"(dst + i*512u), "l"(src + (size_t)i*128) : "memory");
    asm volatile("cp.async.commit_group;" ::: "memory");
}
__device__ __forceinline__ void fill_wait() {
    asm volatile("cp.async.wait_group 0;" ::: "memory");
    __syncwarp();
}

// warp computes 8 output features from its smem weight slot; lane = token.
__device__ __forceinline__ void accum8s(const float* __restrict__ actT,
                                        uint32_t wslot, int lane, ull acc[8]) {
    #pragma unroll
    for (int j = 0; j < 8; j++) acc[j] = 0ULL;
    #pragma unroll 2
    for (int c = 0; c < 8; c++) {
        ull ap[8];
        #pragma unroll
        for (int j = 0; j < 8; j++)
            ap[j] = pk(actT[(c*16 + 2*j)*TP + lane], actT[(c*16 + 2*j + 1)*TP + lane]);
        #pragma unroll
        for (int f = 0; f < 8; f++) {
            uint32_t wr = wslot + f*512 + c*64;
            #pragma unroll
            for (int q = 0; q < 2; q++) {
                ull wa, wb, wc, wd;
                lds2(wr + q*32,      wa, wb);
                lds2(wr + q*32 + 16, wc, wd);
                acc[f] = ffma2(ap[4*q],   wa, acc[f]);
                acc[f] = ffma2(ap[4*q+1], wb, acc[f]);
                acc[f] = ffma2(ap[4*q+2], wc, acc[f]);
                acc[f] = ffma2(ap[4*q+3], wd, acc[f]);
            }
        }
    }
}

// patch embedding: K = 24, weights via LDG (tiny)
__device__ __forceinline__ void accum8p(const float* __restrict__ actT,
                                        const float* __restrict__ w0,
                                        int lane, ull acc[8]) {
    ull ap[12];
    #pragma unroll
    for (int j = 0; j < 12; j++)
        ap[j] = pk(actT[(2*j)*TP + lane], actT[(2*j + 1)*TP + lane]);
    #pragma unroll
    for (int f = 0; f < 8; f++) {
        const float* wr = w0 + f*24;
        acc[f] = 0ULL;
        #pragma unroll
        for (int q = 0; q < 6; q++) {
            ull wa, wb; ldg2(wr + 4*q, wa, wb);
            acc[f] = ffma2(ap[2*q],     wa, acc[f]);
            acc[f] = ffma2(ap[2*q + 1], wb, acc[f]);
        }
    }
}

// transposed layernorm over bufT [128][TP] (tokens in lanes); 2 internal syncs
__device__ __forceinline__ void ln_T(float* bufT, const float* __restrict__ g,
                                     const float* __restrict__ be, float* red) {
    const int tid = threadIdx.x;
    const int t   = tid & 31;
    const int rep = tid >> 5;
    float v[8]; float s = 0.f, q = 0.f;
    #pragma unroll
    for (int j = 0; j < 8; j++) {
        v[j] = bufT[(rep*8 + j)*TP + t];
        s += v[j]; q += v[j]*v[j];
    }
    red[rep*32 + t] = s; red[512 + rep*32 + t] = q;
    __syncthreads();
    if (tid < 32) {
        float S = 0.f, Q = 0.f;
        #pragma unroll
        for (int r2 = 0; r2 < 16; r2++) { S += red[r2*32 + tid]; Q += red[512 + r2*32 + tid]; }
        float m = S * (1.f/128.f);
        float var = Q * (1.f/128.f) - m*m;
        red[1024 + tid] = m;
        red[1056 + tid] = rsqrtf(var + 1e-5f);
    }
    __syncthreads();
    const float m = red[1024 + t], rr = red[1056 + t];
    #pragma unroll
    for (int j = 0; j < 8; j++) {
        int d = rep*8 + j;
        bufT[d*TP + t] = (v[j] - m)*rr*g[d] + be[d];
    }
}

__global__ __launch_bounds__(NT, 1)
void ts_kernel(const float* __restrict__ z,
               const float* __restrict__ WPw, const float* __restrict__ WPb,
               const float* __restrict__ PE,  const float* __restrict__ dummies,
               const float* __restrict__ Wq,  const float* __restrict__ bq,
               const float* __restrict__ Wk,  const float* __restrict__ bk,
               const float* __restrict__ Wv,  const float* __restrict__ bv,
               const float* __restrict__ Wo,  const float* __restrict__ bo,
               const float* __restrict__ g1,  const float* __restrict__ be1,
               const float* __restrict__ W1,  const float* __restrict__ b1,
               const float* __restrict__ W2,  const float* __restrict__ b2,
               const float* __restrict__ g2,  const float* __restrict__ be2,
               const float* __restrict__ Pw,  const float* __restrict__ Pb,
               float* __restrict__ out)
{
    extern __shared__ float sm[];
    float* xT  = sm + OFF_XT;
    float* prT = sm + OFF_PRT;
    float* kT  = sm + OFF_KT;
    float* vT  = sm + OFF_VT;
    float* scr = sm + OFF_SCR;
    float* sco = sm + OFF_SCO;
    float* red = sm + OFF_RED;

    const int tid  = threadIdx.x;
    const int wid  = tid >> 5;
    const int lane = tid & 31;
    const int f0   = wid * 8;
    const int blk  = blockIdx.x;
    const int ch   = blk % CIN;
    const float* zr = z + (size_t)blk * SEQ;

    const uint32_t wslot =
        (uint32_t)__cvta_generic_to_shared(sm + OFF_W) + (uint32_t)wid * 4096u;

    // prefetch layer-0 Wk while we do stats/embedding
    fill_issue(wslot, Wk, f0, lane);

    // -------- instance stats over SEQ --------
    float s1 = 0.f, s2 = 0.f;
    for (int i = tid; i < SEQ; i += NT) { float v = zr[i]; s1 += v; s2 += v*v; }
    #pragma unroll
    for (int o = 16; o; o >>= 1) {
        s1 += __shfl_xor_sync(0xffffffffu, s1, o);
        s2 += __shfl_xor_sync(0xffffffffu, s2, o);
    }
    if (lane == 0) { red[wid] = s1; red[16 + wid] = s2; }
    __syncthreads();
    if (tid == 0) {
        float S1 = 0.f, S2 = 0.f;
        #pragma unroll
        for (int w = 0; w < 16; w++) { S1 += red[w]; S2 += red[16 + w]; }
        float mu  = S1 / (float)SEQ;
        float var = S2 / (float)SEQ - mu*mu;
        float sd  = sqrtf(var + 1e-5f);
        red[1100] = mu; red[1101] = 1.f/sd; red[1102] = sd;
    }
    __syncthreads();
    const float mu = red[1100], rstd = red[1101];

    // -------- stage znT (scratch), peT (kT alias); zero scores --------
    for (int i = tid; i < SEQ; i += NT) {
        int s = i / 24, p = i - s*24;
        scr[p*TP + s] = (zr[i] - mu) * rstd;
    }
    for (int i = tid; i < PN*128; i += NT) {
        kT[(i & 127)*TP + (i >> 7)] = PE[i];        // peT
    }
    for (int i = tid; i < 16*PN*PN; i += NT) sco[i] = 0.f;
    __syncthreads();

    // -------- patch embedding: x (with PE), then pred from dummies --------
    {
        ull acc[8];
        accum8p(scr, WPw + f0*24, lane, acc);
        if (lane < PN) {
            #pragma unroll
            for (int j = 0; j < 8; j++)
                xT[(f0+j)*TP + lane] = fin(acc[j]) + WPb[f0+j] + kT[(f0+j)*TP + lane];
        }
    }
    __syncthreads();
    {
        const float* dm = dummies + (size_t)ch * PN * 24;
        for (int i = tid; i < PN*24; i += NT) {
            int s = i / 24, p = i - s*24;
            scr[p*TP + s] = dm[i];
        }
    }
    __syncthreads();
    {
        ull acc[8];
        accum8p(scr, WPw + f0*24, lane, acc);
        if (lane < PN) {
            #pragma unroll
            for (int j = 0; j < 8; j++)
                prT[(f0+j)*TP + lane] = fin(acc[j]) + WPb[f0+j];
        }
    }
    __syncthreads();

    // -------- transformer layers --------
    #pragma unroll 1
    for (int L = 0; L < 3; L++) {
        const size_t o128 = (size_t)L * 16384;

        // ---- K pass ----
        {
            fill_wait();
            ull ak[8];
            accum8s(xT, wslot, lane, ak);
            fill_issue(wslot, Wv + o128, f0, lane);
            if (lane < PN) {
                #pragma unroll
                for (int j = 0; j < 8; j++)
                    kT[(f0+j)*TP + lane] = fin(ak[j]) + bk[L*128 + f0 + j];
            }
        }
        // ---- V pass ----
        {
            fill_wait();
            ull av[8];
            accum8s(xT, wslot, lane, av);
            fill_issue(wslot, Wq + o128, f0, lane);
            if (lane < PN) {
                #pragma unroll
                for (int j = 0; j < 8; j++)
                    vT[(f0+j)*TP + lane] = fin(av[j]) + bv[L*128 + f0 + j];
            }
        }
        // ---- Q pass -> scr ----
        {
            fill_wait();
            ull aq[8];
            accum8s(prT, wslot, lane, aq);
            fill_issue(wslot, Wo + o128, f0, lane);
            if (lane < PN) {
                #pragma unroll
                for (int j = 0; j < 8; j++)
                    scr[(f0+j)*TP + lane] = fin(aq[j]) + bq[L*128 + f0 + j];
            }
        }
        __syncthreads();

        // ---- attention: warp owns (h,p) rows ----
        {
            const int t = lane;
            for (int r = wid; r < 16*PN; r += 16) {
                const int h = r / PN, p = r - h*PN;
                float qv[8], kv[8];
                #pragma unroll
                for (int j = 0; j < 8; j++) {
                    qv[j] = scr[(h*8+j)*TP + p];      // broadcast
                    kv[j] = kT [(h*8+j)*TP + t];
                }
                float s = 0.f;
                #pragma unroll
                for (int j = 0; j < 8; j++) s += qv[j]*kv[j];
                float* sp = sco + r*PN;
                float sv = -1e30f;
                if (t < PN) { sv = sp[t] + s*SCALEF; sp[t] = sv; }
                float m = sv;
                #pragma unroll
                for (int o = 16; o; o >>= 1) m = fmaxf(m, __shfl_xor_sync(0xffffffffu, m, o));
                float w = (t < PN) ? __expf(sv - m) : 0.f;
                float ssum = w;
                #pragma unroll
                for (int o = 16; o; o >>= 1) ssum += __shfl_xor_sync(0xffffffffu, ssum, o);
                const float inv = 1.f / ssum;
                float ov[8];
                #pragma unroll
                for (int j = 0; j < 8; j++) {
                    float vv = (t < PN) ? vT[(h*8+j)*TP + t] : 0.f;
                    float a = w * vv;
                    #pragma unroll
                    for (int o = 16; o; o >>= 1) a += __shfl_xor_sync(0xffffffffu, a, o);
                    ov[j] = a;
                }
                if (t == 0) {
                    #pragma unroll
                    for (int j = 0; j < 8; j++)
                        scr[(h*8+j)*TP + p] = ov[j] * inv;
                }
            }
        }
        __syncthreads();

        // ---- O pass + residual ----
        {
            fill_wait();
            ull ao[8];
            accum8s(scr, wslot, lane, ao);
            fill_issue(wslot, W1 + (size_t)L*32768, f0, lane);   // W1 a-half
            if (lane < PN) {
                #pragma unroll
                for (int j = 0; j < 8; j++)
                    prT[(f0+j)*TP + lane] += fin(ao[j]) + bo[L*128 + f0 + j];
            }
        }
        __syncthreads();
        ln_T(prT, g1 + L*128, be1 + L*128, red);
        __syncthreads();

        // ---- FFN up: a-half, then gate-half, gelu combine -> scr ----
        {
            fill_wait();
            ull aa[8];
            accum8s(prT, wslot, lane, aa);
            fill_issue(wslot, W1 + (size_t)L*32768 + 16384, f0, lane);  // gate half
            fill_wait();
            ull ag[8];
            accum8s(prT, wslot, lane, ag);
            fill_issue(wslot, W2 + o128, f0, lane);
            if (lane < PN) {
                #pragma unroll
                for (int j = 0; j < 8; j++) {
                    float a  = fin(aa[j]) + b1[L*256 + f0 + j];
                    float gv = fin(ag[j]) + b1[L*256 + 128 + f0 + j];
                    float gel = 0.5f * gv * (1.f + erff(gv * 0.70710678118654752f));
                    scr[(f0+j)*TP + lane] = a * gel;
                }
            }
        }
        __syncthreads();

        // ---- FFN down + residual ----
        {
            fill_wait();
            ull a2[8];
            accum8s(scr, wslot, lane, a2);
            if (L < 2) fill_issue(wslot, Wk + (size_t)(L+1)*16384, f0, lane);
            if (lane < PN) {
                #pragma unroll
                for (int j = 0; j < 8; j++)
                    prT[(f0+j)*TP + lane] += fin(a2[j]) + b2[L*128 + f0 + j];
            }
        }
        __syncthreads();
        ln_T(prT, g2 + L*128, be2 + L*128, red);
        __syncthreads();
    }

    // -------- output head: warps 0..11 handle 2 patch-lanes each --------
    float* outb = sco;   // 720 floats, scores dead now
    if (wid < 12) {
        const int pl0 = wid * 2;
        ull a0 = 0ULL, a1 = 0ULL;
        #pragma unroll 2
        for (int c = 0; c < 8; c++) {
            ull ap[8];
            #pragma unroll
            for (int j = 0; j < 8; j++)
                ap[j] = pk(prT[(c*16 + 2*j)*TP + lane], prT[(c*16 + 2*j + 1)*TP + lane]);
            const float* wr0 = Pw + pl0*128 + c*16;
            const float* wr1 = Pw + (pl0+1)*128 + c*16;
            #pragma unroll
            for (int q = 0; q < 4; q++) {
                ull wa, wb; ldg2(wr0 + 4*q, wa, wb);
                a0 = ffma2(ap[2*q], wa, a0);
                a0 = ffma2(ap[2*q+1], wb, a0);
                ull va, vb; ldg2(wr1 + 4*q, va, vb);
                a1 = ffma2(ap[2*q], va, a1);
                a1 = ffma2(ap[2*q+1], vb, a1);
            }
        }
        if (lane < PN) {
            outb[lane*24 + pl0]     = fin(a0) + Pb[pl0];
            outb[lane*24 + pl0 + 1] = fin(a1) + Pb[pl0 + 1];
        }
    }
    __syncthreads();
    const float sd = red[1102];
    for (int i = tid; i < SEQ; i += NT)
        out[(size_t)blk*SEQ + i] = outb[i]*sd + mu;
}

extern "C" void kernel_launch(void* const* d_in, const int* in_sizes, int n_in,
                              void* d_out, int out_size)
{
    (void)in_sizes; (void)n_in; (void)out_size;
    cudaFuncSetAttribute(ts_kernel, cudaFuncAttributeMaxDynamicSharedMemorySize, SMEM_BYTES);
    ts_kernel<<<16*CIN, NT, SMEM_BYTES>>>(
        (const float*)d_in[0],  (const float*)d_in[1],  (const float*)d_in[2],
        (const float*)d_in[3],  (const float*)d_in[4],  (const float*)d_in[5],
        (const float*)d_in[6],  (const float*)d_in[7],  (const float*)d_in[8],
        (const float*)d_in[9],  (const float*)d_in[10], (const float*)d_in[11],
        (const float*)d_in[12], (const float*)d_in[13], (const float*)d_in[14],
        (const float*)d_in[15], (const float*)d_in[16], (const float*)d_in[17],
        (const float*)d_in[18], (const float*)d_in[19], (const float*)d_in[20],
        (const float*)d_in[21], (const float*)d_in[22],
        (float*)d_out);
}

// round 9
// speedup vs baseline: 2.2435x; 1.2630x over previous
#include <cuda_runtime.h>
#include <cstdint>
#include <math.h>

#define NT     256
#define PN     30
#define TP     33
#define CIN    321
#define SEQ    720
#define NROW   480            // 16 heads * 30 pred tokens
#define SCALEF 0.35355339059327373f   // 8^-0.5

typedef unsigned long long ull;

// persistent raw-score scratch: [item][t(30)][row(480)]
__device__ float scoG[(size_t)16 * CIN * PN * NROW];

// ---------- packed f32x2 helpers ----------
__device__ __forceinline__ ull pk(float lo, float hi) {
    ull r; asm("mov.b64 %0, {%1, %2};" : "=l"(r) : "f"(lo), "f"(hi)); return r;
}
__device__ __forceinline__ float fin(ull a) {
    float x, y; asm("mov.b64 {%0, %1}, %2;" : "=f"(x), "=f"(y) : "l"(a)); return x + y;
}
__device__ __forceinline__ ull ffma2(ull a, ull b, ull c) {
    ull d; asm("fma.rn.f32x2 %0, %1, %2, %3;" : "=l"(d) : "l"(a), "l"(b), "l"(c)); return d;
}
__device__ __forceinline__ void ldg2(const float* p, ull& a, ull& b) {
    asm("ld.global.nc.v2.u64 {%0, %1}, [%2];" : "=l"(a), "=l"(b) : "l"(p));
}
__device__ __forceinline__ void lds2(uint32_t a32, ull& a, ull& b) {
    asm volatile("ld.shared.v2.u64 {%0, %1}, [%2];"
                 : "=l"(a), "=l"(b) : "r"(a32) : "memory");
}

// ---------- smem layout (floats) ----------
#define OFF_XT   0          // x    [128][33]
#define OFF_PRT  4224       // pred [128][33]
#define OFF_KT   8448       // K    [128][33]  (peT at embed; ffn gelu act)
#define OFF_VT   12672      // V    [128][33]  (patches/dummies at embed; ffn a-half)
#define OFF_SCR  16896      // q -> o in place; red alias; outb alias
#define OFF_STG  21120      // weight staging: 8 warps x 2 x 1KB
#define SMEM_FLOATS 25216
#define SMEM_BYTES  (SMEM_FLOATS * 4)   // 100,864 B -> 2 CTAs/SM

// ---------- async weight staging ----------
// chunk = 16 K-values x 16 rows = 1KB. Two ping-pong buffers per warp.
__device__ __forceinline__ void fillc(uint32_t slot, const float* __restrict__ W,
                                      int f0, int ch, int buf, int lane) {
    #pragma unroll
    for (int i = 0; i < 2; i++) {
        int c = lane + 32*i;            // 0..63
        int r = c >> 2, o = c & 3;      // row 0..15, 16B chunk 0..3
        uint32_t dst = slot + (uint32_t)(buf*1024 + r*64 + o*16);
        const float* src = W + (size_t)(f0 + r)*128 + ch*16 + o*4;
        asm volatile("cp.async.cg.shared.global [%0], [%1], 16;"
                     :: "r"(dst), "l"(src) : "memory");
    }
    asm volatile("cp.async.commit_group;" ::: "memory");
}
__device__ __forceinline__ void waitg1() {
    asm volatile("cp.async.wait_group 1;" ::: "memory");
    __syncwarp();
}
__device__ __forceinline__ void waitg0() {
    asm volatile("cp.async.wait_group 0;" ::: "memory");
    __syncwarp();
}

// warp computes 16 output features (rows f0..f0+15, K=128) over 32 token-lanes.
// precondition: fill of Wc chunk 0 -> buf 0 committed.
// postcondition (donext): fill of Wn chunk 0 -> buf 0 committed.
__device__ __forceinline__ void accum16(const float* __restrict__ actT,
                                        const float* __restrict__ Wc,
                                        const float* __restrict__ Wn, bool donext,
                                        uint32_t slot, int f0, int lane, ull acc[16]) {
    #pragma unroll
    for (int j = 0; j < 16; j++) acc[j] = 0ULL;
    #pragma unroll 1
    for (int ch = 0; ch < 8; ch++) {
        bool issued = true;
        if (ch < 7)       fillc(slot, Wc, f0, ch + 1, (ch + 1) & 1, lane);
        else if (donext)  fillc(slot, Wn, f0, 0, 0, lane);
        else              issued = false;
        if (issued) waitg1(); else waitg0();

        const int k0 = ch * 16;
        ull ap[8];
        #pragma unroll
        for (int j = 0; j < 8; j++)
            ap[j] = pk(actT[(k0 + 2*j)*TP + lane], actT[(k0 + 2*j + 1)*TP + lane]);
        const uint32_t base = slot + (uint32_t)((ch & 1) * 1024);
        #pragma unroll
        for (int f = 0; f < 16; f++) {
            uint32_t wr = base + (uint32_t)(f * 64);
            ull w0,w1,w2,w3,w4,w5,w6,w7;
            lds2(wr,      w0, w1);
            lds2(wr + 16, w2, w3);
            lds2(wr + 32, w4, w5);
            lds2(wr + 48, w6, w7);
            acc[f] = ffma2(ap[0], w0, acc[f]);
            acc[f] = ffma2(ap[1], w1, acc[f]);
            acc[f] = ffma2(ap[2], w2, acc[f]);
            acc[f] = ffma2(ap[3], w3, acc[f]);
            acc[f] = ffma2(ap[4], w4, acc[f]);
            acc[f] = ffma2(ap[5], w5, acc[f]);
            acc[f] = ffma2(ap[6], w6, acc[f]);
            acc[f] = ffma2(ap[7], w7, acc[f]);
        }
    }
}

// patch embedding: 16 features, K = 24, weights via uniform LDG
__device__ __forceinline__ void accum16p(const float* __restrict__ actT,
                                         const float* __restrict__ w0,
                                         int lane, ull acc[16]) {
    ull ap[12];
    #pragma unroll
    for (int j = 0; j < 12; j++)
        ap[j] = pk(actT[(2*j)*TP + lane], actT[(2*j + 1)*TP + lane]);
    #pragma unroll
    for (int f = 0; f < 16; f++) {
        const float* wr = w0 + f*24;
        acc[f] = 0ULL;
        #pragma unroll
        for (int q = 0; q < 6; q++) {
            ull wa, wb; ldg2(wr + 4*q, wa, wb);
            acc[f] = ffma2(ap[2*q],     wa, acc[f]);
            acc[f] = ffma2(ap[2*q + 1], wb, acc[f]);
        }
    }
}

// layernorm over feature dim of bufT [128][TP]; red aliases scr (dead there)
__device__ __forceinline__ void ln_T(float* bufT, const float* __restrict__ g,
                                     const float* __restrict__ be, float* red) {
    const int tid = threadIdx.x;
    const int t = tid & 31, w = tid >> 5;
    float v[16]; float s = 0.f, q = 0.f;
    #pragma unroll
    for (int j = 0; j < 16; j++) {
        v[j] = bufT[(w*16 + j)*TP + t];
        s += v[j]; q += v[j]*v[j];
    }
    red[w*32 + t] = s; red[256 + w*32 + t] = q;
    __syncthreads();
    if (tid < 32) {
        float S = 0.f, Q = 0.f;
        #pragma unroll
        for (int r = 0; r < 8; r++) { S += red[r*32 + tid]; Q += red[256 + r*32 + tid]; }
        float m = S * (1.f/128.f);
        float var = Q * (1.f/128.f) - m*m;
        red[512 + tid] = m;
        red[544 + tid] = rsqrtf(var + 1e-5f);
    }
    __syncthreads();
    const float m = red[512 + t], rr = red[544 + t];
    #pragma unroll
    for (int j = 0; j < 16; j++)
        bufT[(w*16 + j)*TP + t] = (v[j] - m)*rr*g[w*16 + j] + be[w*16 + j];
}

__global__ __launch_bounds__(NT, 2)
void ts_kernel(const float* __restrict__ z,
               const float* __restrict__ WPw, const float* __restrict__ WPb,
               const float* __restrict__ PE,  const float* __restrict__ dummies,
               const float* __restrict__ Wq,  const float* __restrict__ bq,
               const float* __restrict__ Wk,  const float* __restrict__ bk,
               const float* __restrict__ Wv,  const float* __restrict__ bv,
               const float* __restrict__ Wo,  const float* __restrict__ bo,
               const float* __restrict__ g1,  const float* __restrict__ be1,
               const float* __restrict__ W1,  const float* __restrict__ b1,
               const float* __restrict__ W2,  const float* __restrict__ b2,
               const float* __restrict__ g2,  const float* __restrict__ be2,
               const float* __restrict__ Pw,  const float* __restrict__ Pb,
               float* __restrict__ out)
{
    extern __shared__ float sm[];
    float* xT  = sm + OFF_XT;
    float* prT = sm + OFF_PRT;
    float* kT  = sm + OFF_KT;
    float* vT  = sm + OFF_VT;
    float* scr = sm + OFF_SCR;
    float* red = scr;                       // alias (scr dead at LN/stats time)

    const int tid  = threadIdx.x;
    const int wid  = tid >> 5;
    const int lane = tid & 31;
    const int f0   = wid * 16;
    const int blk  = blockIdx.x;
    const int ch   = blk % CIN;
    const float* zr = z + (size_t)blk * SEQ;
    float* sgb = scoG + (size_t)blk * (PN * NROW);

    const uint32_t slot =
        (uint32_t)__cvta_generic_to_shared(sm + OFF_STG) + (uint32_t)wid * 2048u;

    // prefetch layer-0 Wk chunk 0 -> buf 0
    fillc(slot, Wk, f0, 0, 0, lane);

    // -------- instance stats over SEQ --------
    float s1 = 0.f, s2 = 0.f;
    for (int i = tid; i < SEQ; i += NT) { float v = zr[i]; s1 += v; s2 += v*v; }
    #pragma unroll
    for (int o = 16; o; o >>= 1) {
        s1 += __shfl_xor_sync(0xffffffffu, s1, o);
        s2 += __shfl_xor_sync(0xffffffffu, s2, o);
    }
    if (lane == 0) { red[wid] = s1; red[8 + wid] = s2; }
    __syncthreads();
    if (tid == 0) {
        float S1 = 0.f, S2 = 0.f;
        #pragma unroll
        for (int w = 0; w < 8; w++) { S1 += red[w]; S2 += red[8 + w]; }
        float m   = S1 / (float)SEQ;
        float var = S2 / (float)SEQ - m*m;
        float sd  = sqrtf(var + 1e-5f);
        red[16] = m; red[17] = 1.f/sd; red[18] = sd;
    }
    __syncthreads();
    const float mu = red[16], rstd = red[17], sd = red[18];
    __syncthreads();

    // -------- stage znT patches into vT, peT into kT --------
    for (int i = tid; i < SEQ; i += NT) {
        int s = i / 24, p = i - s*24;
        vT[p*TP + s] = (zr[i] - mu) * rstd;
    }
    for (int i = tid; i < PN*128; i += NT)
        kT[(i & 127)*TP + (i >> 7)] = PE[i];
    __syncthreads();

    // -------- patch embedding: x (with PE) --------
    {
        ull acc[16];
        accum16p(vT, WPw + f0*24, lane, acc);
        if (lane < PN) {
            #pragma unroll
            for (int j = 0; j < 16; j++)
                xT[(f0+j)*TP + lane] = fin(acc[j]) + WPb[f0+j] + kT[(f0+j)*TP + lane];
        }
    }
    __syncthreads();
    // -------- pred from dummies --------
    {
        const float* dm = dummies + (size_t)ch * PN * 24;
        for (int i = tid; i < PN*24; i += NT) {
            int s = i / 24, p = i - s*24;
            vT[p*TP + s] = dm[i];
        }
        __syncthreads();
        ull acc[16];
        accum16p(vT, WPw + f0*24, lane, acc);
        if (lane < PN) {
            #pragma unroll
            for (int j = 0; j < 16; j++)
                prT[(f0+j)*TP + lane] = fin(acc[j]) + WPb[f0+j];
        }
    }
    __syncthreads();

    // -------- transformer layers --------
    #pragma unroll 1
    for (int L = 0; L < 3; L++) {
        const size_t o128 = (size_t)L * 16384;
        const float* w1a = W1 + (size_t)L * 32768;
        const float* w1g = w1a + 16384;

        // ---- K ----
        {
            ull a[16];
            accum16(xT, Wk + o128, Wv + o128, true, slot, f0, lane, a);
            if (lane < PN) {
                #pragma unroll
                for (int j = 0; j < 16; j++)
                    kT[(f0+j)*TP + lane] = fin(a[j]) + bk[L*128 + f0 + j];
            }
        }
        // ---- V ----
        {
            ull a[16];
            accum16(xT, Wv + o128, Wq + o128, true, slot, f0, lane, a);
            if (lane < PN) {
                #pragma unroll
                for (int j = 0; j < 16; j++)
                    vT[(f0+j)*TP + lane] = fin(a[j]) + bv[L*128 + f0 + j];
            }
        }
        // ---- Q -> scr ----
        {
            ull a[16];
            accum16(prT, Wq + o128, Wo + o128, true, slot, f0, lane, a);
            if (lane < PN) {
                #pragma unroll
                for (int j = 0; j < 16; j++)
                    scr[(f0+j)*TP + lane] = fin(a[j]) + bq[L*128 + f0 + j];
            }
        }
        __syncthreads();

        // ---- attention: thread per (h,p) row; o overwrites own q cells ----
        for (int rr = tid; rr < NROW; rr += NT) {
            const int h = rr / PN, p = rr - h*PN;
            float qv[8];
            #pragma unroll
            for (int j = 0; j < 8; j++) qv[j] = scr[(h*8+j)*TP + p];
            float* sg = sgb + rr;          // stride NROW per t
            float m = -1e30f;
            #pragma unroll 1
            for (int t = 0; t < PN; t++) {
                float s = 0.f;
                #pragma unroll
                for (int j = 0; j < 8; j++) s += qv[j] * kT[(h*8+j)*TP + t];
                s *= SCALEF;
                if (L) s += sg[t*NROW];
                sg[t*NROW] = s;
                m = fmaxf(m, s);
            }
            float ssum = 0.f;
            #pragma unroll 1
            for (int t = 0; t < PN; t++) ssum += __expf(sg[t*NROW] - m);
            const float inv = 1.f / ssum;
            float ov[8];
            #pragma unroll
            for (int j = 0; j < 8; j++) ov[j] = 0.f;
            #pragma unroll 1
            for (int t = 0; t < PN; t++) {
                float w = __expf(sg[t*NROW] - m);
                #pragma unroll
                for (int j = 0; j < 8; j++) ov[j] += w * vT[(h*8+j)*TP + t];
            }
            #pragma unroll
            for (int j = 0; j < 8; j++) scr[(h*8+j)*TP + p] = ov[j] * inv;
        }
        __syncthreads();

        // ---- O + residual ----
        {
            ull a[16];
            accum16(scr, Wo + o128, w1a, true, slot, f0, lane, a);
            if (lane < PN) {
                #pragma unroll
                for (int j = 0; j < 16; j++)
                    prT[(f0+j)*TP + lane] += fin(a[j]) + bo[L*128 + f0 + j];
            }
        }
        __syncthreads();
        ln_T(prT, g1 + L*128, be1 + L*128, red);
        __syncthreads();

        // ---- FFN up a-half -> vT ----
        {
            ull a[16];
            accum16(prT, w1a, w1g, true, slot, f0, lane, a);
            if (lane < PN) {
                #pragma unroll
                for (int j = 0; j < 16; j++)
                    vT[(f0+j)*TP + lane] = fin(a[j]) + b1[L*256 + f0 + j];
            }
        }
        // ---- FFN up gate-half; gelu combine -> kT ----
        {
            ull a[16];
            accum16(prT, w1g, W2 + o128, true, slot, f0, lane, a);
            if (lane < PN) {
                #pragma unroll
                for (int j = 0; j < 16; j++) {
                    float av  = vT[(f0+j)*TP + lane];
                    float gv  = fin(a[j]) + b1[L*256 + 128 + f0 + j];
                    float gel = 0.5f * gv * (1.f + erff(gv * 0.70710678118654752f));
                    kT[(f0+j)*TP + lane] = av * gel;
                }
            }
        }
        __syncthreads();

        // ---- FFN down + residual ----
        {
            ull a[16];
            accum16(kT, W2 + o128, Wk + (size_t)(L+1)*16384, L < 2, slot, f0, lane, a);
            if (lane < PN) {
                #pragma unroll
                for (int j = 0; j < 16; j++)
                    prT[(f0+j)*TP + lane] += fin(a[j]) + b2[L*128 + f0 + j];
            }
        }
        __syncthreads();
        ln_T(prT, g2 + L*128, be2 + L*128, red);
        __syncthreads();
    }

    // -------- output head: 8 warps x 3 patch-lanes; outb aliases scr --------
    float* outb = scr;
    {
        const int pl0 = wid * 3;
        ull a0 = 0ULL, a1 = 0ULL, a2 = 0ULL;
        #pragma unroll 2
        for (int c = 0; c < 8; c++) {
            ull ap[8];
            #pragma unroll
            for (int j = 0; j < 8; j++)
                ap[j] = pk(prT[(c*16 + 2*j)*TP + lane], prT[(c*16 + 2*j + 1)*TP + lane]);
            const float* wr0 = Pw + (pl0    )*128 + c*16;
            const float* wr1 = Pw + (pl0 + 1)*128 + c*16;
            const float* wr2 = Pw + (pl0 + 2)*128 + c*16;
            #pragma unroll
            for (int q = 0; q < 4; q++) {
                ull wa, wb;
                ldg2(wr0 + 4*q, wa, wb);
                a0 = ffma2(ap[2*q], wa, a0); a0 = ffma2(ap[2*q+1], wb, a0);
                ldg2(wr1 + 4*q, wa, wb);
                a1 = ffma2(ap[2*q], wa, a1); a1 = ffma2(ap[2*q+1], wb, a1);
                ldg2(wr2 + 4*q, wa, wb);
                a2 = ffma2(ap[2*q], wa, a2); a2 = ffma2(ap[2*q+1], wb, a2);
            }
        }
        if (lane < PN) {
            outb[lane*24 + pl0    ] = fin(a0) + Pb[pl0];
            outb[lane*24 + pl0 + 1] = fin(a1) + Pb[pl0 + 1];
            outb[lane*24 + pl0 + 2] = fin(a2) + Pb[pl0 + 2];
        }
    }
    __syncthreads();
    for (int i = tid; i < SEQ; i += NT)
        out[(size_t)blk*SEQ + i] = outb[i]*sd + mu;
}

extern "C" void kernel_launch(void* const* d_in, const int* in_sizes, int n_in,
                              void* d_out, int out_size)
{
    (void)in_sizes; (void)n_in; (void)out_size;
    cudaFuncSetAttribute(ts_kernel, cudaFuncAttributeMaxDynamicSharedMemorySize, SMEM_BYTES);
    ts_kernel<<<16*CIN, NT, SMEM_BYTES>>>(
        (const float*)d_in[0],  (const float*)d_in[1],  (const float*)d_in[2],
        (const float*)d_in[3],  (const float*)d_in[4],  (const float*)d_in[5],
        (const float*)d_in[6],  (const float*)d_in[7],  (const float*)d_in[8],
        (const float*)d_in[9],  (const float*)d_in[10], (const float*)d_in[11],
        (const float*)d_in[12], (const float*)d_in[13], (const float*)d_in[14],
        (const float*)d_in[15], (const float*)d_in[16], (const float*)d_in[17],
        (const float*)d_in[18], (const float*)d_in[19], (const float*)d_in[20],
        (const float*)d_in[21], (const float*)d_in[22],
        (float*)d_out);
}

// round 10
// speedup vs baseline: 2.7756x; 1.2372x over previous
#include <cuda_runtime.h>
#include <cstdint>
#include <math.h>

#define NT     512
#define PN     30
#define TP     33
#define CIN    321
#define SEQ    720
#define NROW   480            // 16 heads * 30 pred tokens
#define ITEMS  5136
#define ISTR   21120          // per-item smem float stride
#define SCALEF 0.35355339059327373f   // 8^-0.5

typedef unsigned long long ull;

// persistent raw-score scratch: [item][t(30)][row(480)]
__device__ float scoG[(size_t)ITEMS * PN * NROW];

// ---------- packed f32x2 helpers ----------
__device__ __forceinline__ ull pk(float lo, float hi) {
    ull r; asm("mov.b64 %0, {%1, %2};" : "=l"(r) : "f"(lo), "f"(hi)); return r;
}
__device__ __forceinline__ float fin(ull a) {
    float x, y; asm("mov.b64 {%0, %1}, %2;" : "=f"(x), "=f"(y) : "l"(a)); return x + y;
}
__device__ __forceinline__ ull ffma2(ull a, ull b, ull c) {
    ull d; asm("fma.rn.f32x2 %0, %1, %2, %3;" : "=l"(d) : "l"(a), "l"(b), "l"(c)); return d;
}
__device__ __forceinline__ void ldg2(const float* p, ull& a, ull& b) {
    asm("ld.global.nc.v2.u64 {%0, %1}, [%2];" : "=l"(a), "=l"(b) : "l"(p));
}
__device__ __forceinline__ void lds2(uint32_t a32, ull& a, ull& b) {
    asm volatile("ld.shared.v2.u64 {%0, %1}, [%2];"
                 : "=l"(a), "=l"(b) : "r"(a32) : "memory");
}

// ---------- smem layout (floats) ----------
// per item (stride ISTR): xT 0 | prT 4224 | kT 8448 | vT 12672 | scr 16896
#define OFF_XT   0
#define OFF_PRT  4224
#define OFF_KT   8448
#define OFF_VT   12672
#define OFF_SCR  16896
#define OFF_STG  42240       // 16 warps x 256 floats (2 x 512B ping-pong)
#define SMEM_FLOATS 46336
#define SMEM_BYTES  (SMEM_FLOATS * 4)    // 185,344 B -> 1 CTA/SM

// ---------- async weight staging ----------
// chunk = 16 K-values x 8 rows = 512B. Two ping-pong buffers per warp.
__device__ __forceinline__ void fillc(uint32_t slot, const float* __restrict__ W,
                                      int f0, int ch, int buf, int lane) {
    int r = lane >> 2, o = lane & 3;      // row 0..7, 16B chunk 0..3
    uint32_t dst = slot + (uint32_t)(buf*512 + r*64 + o*16);
    const float* src = W + (size_t)(f0 + r)*128 + ch*16 + o*4;
    asm volatile("cp.async.cg.shared.global [%0], [%1], 16;"
                 :: "r"(dst), "l"(src) : "memory");
    asm volatile("cp.async.commit_group;" ::: "memory");
}
__device__ __forceinline__ void waitg1() {
    asm volatile("cp.async.wait_group 1;" ::: "memory");
    __syncwarp();
}
__device__ __forceinline__ void waitg0() {
    asm volatile("cp.async.wait_group 0;" ::: "memory");
    __syncwarp();
}

// warp computes 8 output features (rows f0..f0+7, K=128) for BOTH items.
// precondition: fill of Wc chunk 0 -> buf 0 committed.
// postcondition (donext): fill of Wn chunk 0 -> buf 0 committed.
__device__ __forceinline__ void accum8d2(const float* __restrict__ aA,
                                         const float* __restrict__ aB,
                                         const float* __restrict__ Wc,
                                         const float* __restrict__ Wn, bool donext,
                                         uint32_t slot, int f0, int lane,
                                         ull accA[8], ull accB[8]) {
    #pragma unroll
    for (int j = 0; j < 8; j++) { accA[j] = 0ULL; accB[j] = 0ULL; }
    #pragma unroll 1
    for (int ch = 0; ch < 8; ch++) {
        bool issued = true;
        if (ch < 7)       fillc(slot, Wc, f0, ch + 1, (ch + 1) & 1, lane);
        else if (donext)  fillc(slot, Wn, f0, 0, 0, lane);
        else              issued = false;
        if (issued) waitg1(); else waitg0();

        const int k0 = ch * 16;
        ull apA[8], apB[8];
        #pragma unroll
        for (int j = 0; j < 8; j++) {
            apA[j] = pk(aA[(k0 + 2*j)*TP + lane], aA[(k0 + 2*j + 1)*TP + lane]);
            apB[j] = pk(aB[(k0 + 2*j)*TP + lane], aB[(k0 + 2*j + 1)*TP + lane]);
        }
        const uint32_t base = slot + (uint32_t)((ch & 1) * 512);
        #pragma unroll
        for (int f = 0; f < 8; f++) {
            uint32_t wr = base + (uint32_t)(f * 64);
            ull w0,w1,w2,w3,w4,w5,w6,w7;
            lds2(wr,      w0, w1);
            lds2(wr + 16, w2, w3);
            lds2(wr + 32, w4, w5);
            lds2(wr + 48, w6, w7);
            accA[f] = ffma2(apA[0], w0, accA[f]);
            accA[f] = ffma2(apA[1], w1, accA[f]);
            accA[f] = ffma2(apA[2], w2, accA[f]);
            accA[f] = ffma2(apA[3], w3, accA[f]);
            accA[f] = ffma2(apA[4], w4, accA[f]);
            accA[f] = ffma2(apA[5], w5, accA[f]);
            accA[f] = ffma2(apA[6], w6, accA[f]);
            accA[f] = ffma2(apA[7], w7, accA[f]);
            accB[f] = ffma2(apB[0], w0, accB[f]);
            accB[f] = ffma2(apB[1], w1, accB[f]);
            accB[f] = ffma2(apB[2], w2, accB[f]);
            accB[f] = ffma2(apB[3], w3, accB[f]);
            accB[f] = ffma2(apB[4], w4, accB[f]);
            accB[f] = ffma2(apB[5], w5, accB[f]);
            accB[f] = ffma2(apB[6], w6, accB[f]);
            accB[f] = ffma2(apB[7], w7, accB[f]);
        }
    }
}

// patch embedding: 8 features, K = 24, dual item, weights via uniform LDG
__device__ __forceinline__ void accum8p2(const float* __restrict__ aA,
                                         const float* __restrict__ aB,
                                         const float* __restrict__ w0,
                                         int lane, ull accA[8], ull accB[8]) {
    ull apA[12], apB[12];
    #pragma unroll
    for (int j = 0; j < 12; j++) {
        apA[j] = pk(aA[(2*j)*TP + lane], aA[(2*j + 1)*TP + lane]);
        apB[j] = pk(aB[(2*j)*TP + lane], aB[(2*j + 1)*TP + lane]);
    }
    #pragma unroll
    for (int f = 0; f < 8; f++) {
        const float* wr = w0 + f*24;
        accA[f] = 0ULL; accB[f] = 0ULL;
        #pragma unroll
        for (int q = 0; q < 6; q++) {
            ull wa, wb; ldg2(wr + 4*q, wa, wb);
            accA[f] = ffma2(apA[2*q],     wa, accA[f]);
            accA[f] = ffma2(apA[2*q + 1], wb, accA[f]);
            accB[f] = ffma2(apB[2*q],     wa, accB[f]);
            accB[f] = ffma2(apB[2*q + 1], wb, accB[f]);
        }
    }
}

// layernorm per item over feature dim of bufT [128][TP]; 256 threads per item.
// red aliases the item's scr region (dead at LN time). tid2 = tid & 255.
__device__ __forceinline__ void ln_T(float* bufT, const float* __restrict__ g,
                                     const float* __restrict__ be, float* red,
                                     int tid2) {
    const int t = tid2 & 31, w = tid2 >> 5;
    float v[16]; float s = 0.f, q = 0.f;
    #pragma unroll
    for (int j = 0; j < 16; j++) {
        v[j] = bufT[(w*16 + j)*TP + t];
        s += v[j]; q += v[j]*v[j];
    }
    red[w*32 + t] = s; red[256 + w*32 + t] = q;
    __syncthreads();
    if (tid2 < 32) {
        float S = 0.f, Q = 0.f;
        #pragma unroll
        for (int r = 0; r < 8; r++) { S += red[r*32 + tid2]; Q += red[256 + r*32 + tid2]; }
        float m = S * (1.f/128.f);
        float var = Q * (1.f/128.f) - m*m;
        red[512 + tid2] = m;
        red[544 + tid2] = rsqrtf(var + 1e-5f);
    }
    __syncthreads();
    const float m = red[512 + t], rr = red[544 + t];
    #pragma unroll
    for (int j = 0; j < 16; j++)
        bufT[(w*16 + j)*TP + t] = (v[j] - m)*rr*g[w*16 + j] + be[w*16 + j];
}

__global__ __launch_bounds__(NT, 1)
void ts_kernel(const float* __restrict__ z,
               const float* __restrict__ WPw, const float* __restrict__ WPb,
               const float* __restrict__ PE,  const float* __restrict__ dummies,
               const float* __restrict__ Wq,  const float* __restrict__ bq,
               const float* __restrict__ Wk,  const float* __restrict__ bk,
               const float* __restrict__ Wv,  const float* __restrict__ bv,
               const float* __restrict__ Wo,  const float* __restrict__ bo,
               const float* __restrict__ g1,  const float* __restrict__ be1,
               const float* __restrict__ W1,  const float* __restrict__ b1,
               const float* __restrict__ W2,  const float* __restrict__ b2,
               const float* __restrict__ g2,  const float* __restrict__ be2,
               const float* __restrict__ Pw,  const float* __restrict__ Pb,
               float* __restrict__ out)
{
    extern __shared__ float sm[];
    // item-A buffers (item-B at +ISTR)
    float* xT  = sm + OFF_XT;
    float* prT = sm + OFF_PRT;
    float* kT  = sm + OFF_KT;
    float* vT  = sm + OFF_VT;
    float* scr = sm + OFF_SCR;

    const int tid  = threadIdx.x;
    const int wid  = tid >> 5;
    const int lane = tid & 31;
    const int f0   = wid * 8;          // each warp: 8 features, both items
    const int blk  = blockIdx.x;

    const int half = tid >> 8;         // 0 = item A, 1 = item B (for per-item phases)
    const int tid2 = tid & 255;
    const int item = blk*2 + half;
    const int chn  = item % CIN;
    const float* zr = z + (size_t)item * SEQ;
    float* hb = sm + half * ISTR;      // this thread's item base

    const uint32_t slot =
        (uint32_t)__cvta_generic_to_shared(sm + OFF_STG) + (uint32_t)wid * 1024u;

    // prefetch layer-0 Wk chunk 0 -> buf 0
    fillc(slot, Wk, f0, 0, 0, lane);

    // -------- instance stats (per item, 8 warps each) --------
    float* redh = hb + OFF_SCR;
    float s1 = 0.f, s2 = 0.f;
    for (int i = tid2; i < SEQ; i += 256) { float v = zr[i]; s1 += v; s2 += v*v; }
    #pragma unroll
    for (int o = 16; o; o >>= 1) {
        s1 += __shfl_xor_sync(0xffffffffu, s1, o);
        s2 += __shfl_xor_sync(0xffffffffu, s2, o);
    }
    if (lane == 0) { redh[tid2 >> 5] = s1; redh[8 + (tid2 >> 5)] = s2; }
    __syncthreads();
    if (tid2 == 0) {
        float S1 = 0.f, S2 = 0.f;
        #pragma unroll
        for (int w = 0; w < 8; w++) { S1 += redh[w]; S2 += redh[8 + w]; }
        float m   = S1 / (float)SEQ;
        float var = S2 / (float)SEQ - m*m;
        float sd  = sqrtf(var + 1e-5f);
        redh[16] = m; redh[17] = 1.f/sd; redh[18] = sd;
    }
    __syncthreads();
    const float mu = redh[16], rstd = redh[17], sd = redh[18];
    __syncthreads();

    // -------- stage znT patches into item's vT; PE once into item-A kT --------
    for (int i = tid2; i < SEQ; i += 256) {
        int s = i / 24, p = i - s*24;
        hb[OFF_VT + p*TP + s] = (zr[i] - mu) * rstd;
    }
    for (int i = tid; i < PN*128; i += NT)
        kT[(i & 127)*TP + (i >> 7)] = PE[i];   // item-A kT holds PE for both
    __syncthreads();

    // -------- patch embedding: x = W_P*patches + b + PE (dual) --------
    {
        ull aA[8], aB[8];
        accum8p2(vT, vT + ISTR, WPw + f0*24, lane, aA, aB);
        if (lane < PN) {
            #pragma unroll
            for (int j = 0; j < 8; j++) {
                float pe = kT[(f0+j)*TP + lane], bb = WPb[f0+j];
                xT[(f0+j)*TP + lane]        = fin(aA[j]) + bb + pe;
                xT[ISTR + (f0+j)*TP + lane] = fin(aB[j]) + bb + pe;
            }
        }
    }
    __syncthreads();
    // -------- pred from dummies (per-item channel) --------
    {
        const float* dm = dummies + (size_t)chn * PN * 24;
        for (int i = tid2; i < PN*24; i += 256) {
            int s = i / 24, p = i - s*24;
            hb[OFF_VT + p*TP + s] = dm[i];
        }
        __syncthreads();
        ull aA[8], aB[8];
        accum8p2(vT, vT + ISTR, WPw + f0*24, lane, aA, aB);
        if (lane < PN) {
            #pragma unroll
            for (int j = 0; j < 8; j++) {
                float bb = WPb[f0+j];
                prT[(f0+j)*TP + lane]        = fin(aA[j]) + bb;
                prT[ISTR + (f0+j)*TP + lane] = fin(aB[j]) + bb;
            }
        }
    }
    __syncthreads();

    // -------- transformer layers --------
    #pragma unroll 1
    for (int L = 0; L < 3; L++) {
        const size_t o128 = (size_t)L * 16384;
        const float* w1a = W1 + (size_t)L * 32768;
        const float* w1g = w1a + 16384;

        // ---- K ----
        {
            ull aA[8], aB[8];
            accum8d2(xT, xT + ISTR, Wk + o128, Wv + o128, true, slot, f0, lane, aA, aB);
            if (lane < PN) {
                #pragma unroll
                for (int j = 0; j < 8; j++) {
                    float bb = bk[L*128 + f0 + j];
                    kT[(f0+j)*TP + lane]        = fin(aA[j]) + bb;
                    kT[ISTR + (f0+j)*TP + lane] = fin(aB[j]) + bb;
                }
            }
        }
        // ---- V ----
        {
            ull aA[8], aB[8];
            accum8d2(xT, xT + ISTR, Wv + o128, Wq + o128, true, slot, f0, lane, aA, aB);
            if (lane < PN) {
                #pragma unroll
                for (int j = 0; j < 8; j++) {
                    float bb = bv[L*128 + f0 + j];
                    vT[(f0+j)*TP + lane]        = fin(aA[j]) + bb;
                    vT[ISTR + (f0+j)*TP + lane] = fin(aB[j]) + bb;
                }
            }
        }
        // ---- Q -> scr ----
        {
            ull aA[8], aB[8];
            accum8d2(prT, prT + ISTR, Wq + o128, Wo + o128, true, slot, f0, lane, aA, aB);
            if (lane < PN) {
                #pragma unroll
                for (int j = 0; j < 8; j++) {
                    float bb = bq[L*128 + f0 + j];
                    scr[(f0+j)*TP + lane]        = fin(aA[j]) + bb;
                    scr[ISTR + (f0+j)*TP + lane] = fin(aB[j]) + bb;
                }
            }
        }
        __syncthreads();

        // ---- attention: thread per (h,p,item) row; o overwrites own q cells ----
        for (int rr = tid; rr < 2*NROW; rr += NT) {
            const int it = rr >= NROW;
            const int r0 = rr - it*NROW;
            const int h = r0 / PN, p = r0 - h*PN;
            float* ib = sm + it * ISTR;
            float* sg = scoG + (size_t)(blk*2 + it) * (PN*NROW) + r0;
            float qv[8];
            #pragma unroll
            for (int j = 0; j < 8; j++) qv[j] = ib[OFF_SCR + (h*8+j)*TP + p];
            float m = -1e30f;
            #pragma unroll 1
            for (int t = 0; t < PN; t++) {
                float s = 0.f;
                #pragma unroll
                for (int j = 0; j < 8; j++) s += qv[j] * ib[OFF_KT + (h*8+j)*TP + t];
                s *= SCALEF;
                if (L) s += sg[t*NROW];
                sg[t*NROW] = s;
                m = fmaxf(m, s);
            }
            float ssum = 0.f;
            #pragma unroll 1
            for (int t = 0; t < PN; t++) ssum += __expf(sg[t*NROW] - m);
            const float inv = 1.f / ssum;
            float ov[8];
            #pragma unroll
            for (int j = 0; j < 8; j++) ov[j] = 0.f;
            #pragma unroll 1
            for (int t = 0; t < PN; t++) {
                float w = __expf(sg[t*NROW] - m);
                #pragma unroll
                for (int j = 0; j < 8; j++) ov[j] += w * ib[OFF_VT + (h*8+j)*TP + t];
            }
            #pragma unroll
            for (int j = 0; j < 8; j++) ib[OFF_SCR + (h*8+j)*TP + p] = ov[j] * inv;
        }
        __syncthreads();

        // ---- O + residual ----
        {
            ull aA[8], aB[8];
            accum8d2(scr, scr + ISTR, Wo + o128, w1a, true, slot, f0, lane, aA, aB);
            if (lane < PN) {
                #pragma unroll
                for (int j = 0; j < 8; j++) {
                    float bb = bo[L*128 + f0 + j];
                    prT[(f0+j)*TP + lane]        += fin(aA[j]) + bb;
                    prT[ISTR + (f0+j)*TP + lane] += fin(aB[j]) + bb;
                }
            }
        }
        __syncthreads();
        ln_T(hb + OFF_PRT, g1 + L*128, be1 + L*128, hb + OFF_SCR, tid2);
        __syncthreads();

        // ---- FFN up a-half -> vT ----
        {
            ull aA[8], aB[8];
            accum8d2(prT, prT + ISTR, w1a, w1g, true, slot, f0, lane, aA, aB);
            if (lane < PN) {
                #pragma unroll
                for (int j = 0; j < 8; j++) {
                    float bb = b1[L*256 + f0 + j];
                    vT[(f0+j)*TP + lane]        = fin(aA[j]) + bb;
                    vT[ISTR + (f0+j)*TP + lane] = fin(aB[j]) + bb;
                }
            }
        }
        // ---- FFN up gate-half; gelu combine -> kT ----
        {
            ull aA[8], aB[8];
            accum8d2(prT, prT + ISTR, w1g, W2 + o128, true, slot, f0, lane, aA, aB);
            if (lane < PN) {
                #pragma unroll
                for (int j = 0; j < 8; j++) {
                    float bb = b1[L*256 + 128 + f0 + j];
                    float gA = fin(aA[j]) + bb;
                    float gB = fin(aB[j]) + bb;
                    float eA = 0.5f * gA * (1.f + erff(gA * 0.70710678118654752f));
                    float eB = 0.5f * gB * (1.f + erff(gB * 0.70710678118654752f));
                    kT[(f0+j)*TP + lane]        = vT[(f0+j)*TP + lane] * eA;
                    kT[ISTR + (f0+j)*TP + lane] = vT[ISTR + (f0+j)*TP + lane] * eB;
                }
            }
        }
        __syncthreads();

        // ---- FFN down + residual ----
        {
            ull aA[8], aB[8];
            accum8d2(kT, kT + ISTR, W2 + o128, Wk + (size_t)(L+1)*16384, L < 2,
                     slot, f0, lane, aA, aB);
            if (lane < PN) {
                #pragma unroll
                for (int j = 0; j < 8; j++) {
                    float bb = b2[L*128 + f0 + j];
                    prT[(f0+j)*TP + lane]        += fin(aA[j]) + bb;
                    prT[ISTR + (f0+j)*TP + lane] += fin(aB[j]) + bb;
                }
            }
        }
        __syncthreads();
        ln_T(hb + OFF_PRT, g2 + L*128, be2 + L*128, hb + OFF_SCR, tid2);
        __syncthreads();
    }

    // -------- output head: warp-halves per item, 3 patch-lanes/warp --------
    {
        const int hit  = wid >> 3;          // head item for this warp
        const int pl0  = (wid & 7) * 3;
        const float* pT = sm + hit*ISTR + OFF_PRT;
        float* outb     = sm + hit*ISTR + OFF_SCR;
        ull a0 = 0ULL, a1 = 0ULL, a2 = 0ULL;
        #pragma unroll 2
        for (int c = 0; c < 8; c++) {
            ull ap[8];
            #pragma unroll
            for (int j = 0; j < 8; j++)
                ap[j] = pk(pT[(c*16 + 2*j)*TP + lane], pT[(c*16 + 2*j + 1)*TP + lane]);
            const float* wr0 = Pw + (pl0    )*128 + c*16;
            const float* wr1 = Pw + (pl0 + 1)*128 + c*16;
            const float* wr2 = Pw + (pl0 + 2)*128 + c*16;
            #pragma unroll
            for (int q = 0; q < 4; q++) {
                ull wa, wb;
                ldg2(wr0 + 4*q, wa, wb);
                a0 = ffma2(ap[2*q], wa, a0); a0 = ffma2(ap[2*q+1], wb, a0);
                ldg2(wr1 + 4*q, wa, wb);
                a1 = ffma2(ap[2*q], wa, a1); a1 = ffma2(ap[2*q+1], wb, a1);
                ldg2(wr2 + 4*q, wa, wb);
                a2 = ffma2(ap[2*q], wa, a2); a2 = ffma2(ap[2*q+1], wb, a2);
            }
        }
        if (lane < PN) {
            outb[lane*24 + pl0    ] = fin(a0) + Pb[pl0];
            outb[lane*24 + pl0 + 1] = fin(a1) + Pb[pl0 + 1];
            outb[lane*24 + pl0 + 2] = fin(a2) + Pb[pl0 + 2];
        }
    }
    __syncthreads();
    {
        const float* outb = hb + OFF_SCR;
        for (int i = tid2; i < SEQ; i += 256)
            out[(size_t)item*SEQ + i] = outb[i]*sd + mu;
    }
}

extern "C" void kernel_launch(void* const* d_in, const int* in_sizes, int n_in,
                              void* d_out, int out_size)
{
    (void)in_sizes; (void)n_in; (void)out_size;
    cudaFuncSetAttribute(ts_kernel, cudaFuncAttributeMaxDynamicSharedMemorySize, SMEM_BYTES);
    ts_kernel<<<ITEMS/2, NT, SMEM_BYTES>>>(
        (const float*)d_in[0],  (const float*)d_in[1],  (const float*)d_in[2],
        (const float*)d_in[3],  (const float*)d_in[4],  (const float*)d_in[5],
        (const float*)d_in[6],  (const float*)d_in[7],  (const float*)d_in[8],
        (const float*)d_in[9],  (const float*)d_in[10], (const float*)d_in[11],
        (const float*)d_in[12], (const float*)d_in[13], (const float*)d_in[14],
        (const float*)d_in[15], (const float*)d_in[16], (const float*)d_in[17],
        (const float*)d_in[18], (const float*)d_in[19], (const float*)d_in[20],
        (const float*)d_in[21], (const float*)d_in[22],
        (float*)d_out);
}

// round 11
// speedup vs baseline: 3.0114x; 1.0849x over previous
#include <cuda_runtime.h>
#include <cstdint>
#include <math.h>

#define NT     512
#define PN     30
#define TP     33            // pair-row stride (in float2 units)
#define CIN    321
#define SEQ    720
#define NROW   480
#define ITEMS  5136
#define ISTR   21120
#define SCALEF 0.35355339059327373f   // 8^-0.5

typedef unsigned long long ull;

// persistent raw-score scratch: [item][t(30)][row(480)]
__device__ float scoG[(size_t)ITEMS * PN * NROW];

// ---------- packed f32x2 helpers ----------
__device__ __forceinline__ ull pk(float lo, float hi) {
    ull r; asm("mov.b64 %0, {%1, %2};" : "=l"(r) : "f"(lo), "f"(hi)); return r;
}
__device__ __forceinline__ float fin(ull a) {
    float x, y; asm("mov.b64 {%0, %1}, %2;" : "=f"(x), "=f"(y) : "l"(a)); return x + y;
}
__device__ __forceinline__ void up2(ull a, float& x, float& y) {
    asm("mov.b64 {%0, %1}, %2;" : "=f"(x), "=f"(y) : "l"(a));
}
__device__ __forceinline__ ull ffma2(ull a, ull b, ull c) {
    ull d; asm("fma.rn.f32x2 %0, %1, %2, %3;" : "=l"(d) : "l"(a), "l"(b), "l"(c)); return d;
}
__device__ __forceinline__ void ldg2(const float* p, ull& a, ull& b) {
    asm("ld.global.nc.v2.u64 {%0, %1}, [%2];" : "=l"(a), "=l"(b) : "l"(p));
}
__device__ __forceinline__ void lds2(uint32_t a32, ull& a, ull& b) {
    asm volatile("ld.shared.v2.u64 {%0, %1}, [%2];"
                 : "=l"(a), "=l"(b) : "r"(a32) : "memory");
}
// paired activation accessors: buffer holds [64 pairs][TP tokens] float2
__device__ __forceinline__ ull ldp(const float* b, int fp, int t) {
    return *(const ull*)(b + (fp*TP + t)*2);
}
__device__ __forceinline__ void stp(float* b, int fp, int t, ull v) {
    *(ull*)(b + (fp*TP + t)*2) = v;
}

// ---------- smem layout (floats) ----------
// per item (stride ISTR): xT 0 | prT 4224 | kT 8448 | vT 12672 | scr 16896
#define OFF_XT   0
#define OFF_PRT  4224
#define OFF_KT   8448
#define OFF_VT   12672
#define OFF_SCR  16896
#define OFF_STG  42240       // 16 warps x 256 floats (2 x 512B ping-pong)
#define SMEM_FLOATS 46336
#define SMEM_BYTES  (SMEM_FLOATS * 4)    // 185,344 B -> 1 CTA/SM

// ---------- async weight staging (unchanged discipline from R9/R10) ----------
__device__ __forceinline__ void fillc(uint32_t slot, const float* __restrict__ W,
                                      int f0, int ch, int buf, int lane) {
    int r = lane >> 2, o = lane & 3;
    uint32_t dst = slot + (uint32_t)(buf*512 + r*64 + o*16);
    const float* src = W + (size_t)(f0 + r)*128 + ch*16 + o*4;
    asm volatile("cp.async.cg.shared.global [%0], [%1], 16;"
                 :: "r"(dst), "l"(src) : "memory");
    asm volatile("cp.async.commit_group;" ::: "memory");
}
__device__ __forceinline__ void waitg1() {
    asm volatile("cp.async.wait_group 1;" ::: "memory");
    __syncwarp();
}
__device__ __forceinline__ void waitg0() {
    asm volatile("cp.async.wait_group 0;" ::: "memory");
    __syncwarp();
}

// warp computes 8 output features (rows f0..f0+7, K=128) for BOTH items.
__device__ __forceinline__ void accum8d2(const float* __restrict__ aA,
                                         const float* __restrict__ aB,
                                         const float* __restrict__ Wc,
                                         const float* __restrict__ Wn, bool donext,
                                         uint32_t slot, int f0, int lane,
                                         ull accA[8], ull accB[8]) {
    #pragma unroll
    for (int j = 0; j < 8; j++) { accA[j] = 0ULL; accB[j] = 0ULL; }
    #pragma unroll 1
    for (int ch = 0; ch < 8; ch++) {
        bool issued = true;
        if (ch < 7)       fillc(slot, Wc, f0, ch + 1, (ch + 1) & 1, lane);
        else if (donext)  fillc(slot, Wn, f0, 0, 0, lane);
        else              issued = false;
        if (issued) waitg1(); else waitg0();

        ull apA[8], apB[8];
        #pragma unroll
        for (int j = 0; j < 8; j++) {
            apA[j] = ldp(aA, ch*8 + j, lane);
            apB[j] = ldp(aB, ch*8 + j, lane);
        }
        const uint32_t base = slot + (uint32_t)((ch & 1) * 512);
        #pragma unroll
        for (int f = 0; f < 8; f++) {
            uint32_t wr = base + (uint32_t)(f * 64);
            ull w0,w1,w2,w3,w4,w5,w6,w7;
            lds2(wr,      w0, w1);
            lds2(wr + 16, w2, w3);
            lds2(wr + 32, w4, w5);
            lds2(wr + 48, w6, w7);
            accA[f] = ffma2(apA[0], w0, accA[f]);
            accA[f] = ffma2(apA[1], w1, accA[f]);
            accA[f] = ffma2(apA[2], w2, accA[f]);
            accA[f] = ffma2(apA[3], w3, accA[f]);
            accA[f] = ffma2(apA[4], w4, accA[f]);
            accA[f] = ffma2(apA[5], w5, accA[f]);
            accA[f] = ffma2(apA[6], w6, accA[f]);
            accA[f] = ffma2(apA[7], w7, accA[f]);
            accB[f] = ffma2(apB[0], w0, accB[f]);
            accB[f] = ffma2(apB[1], w1, accB[f]);
            accB[f] = ffma2(apB[2], w2, accB[f]);
            accB[f] = ffma2(apB[3], w3, accB[f]);
            accB[f] = ffma2(apB[4], w4, accB[f]);
            accB[f] = ffma2(apB[5], w5, accB[f]);
            accB[f] = ffma2(apB[6], w6, accB[f]);
            accB[f] = ffma2(apB[7], w7, accB[f]);
        }
    }
}

// patch embedding: 8 features, K = 24 (12 pairs), dual item, weights via LDG
__device__ __forceinline__ void accum8p2(const float* __restrict__ aA,
                                         const float* __restrict__ aB,
                                         const float* __restrict__ w0,
                                         int lane, ull accA[8], ull accB[8]) {
    ull apA[12], apB[12];
    #pragma unroll
    for (int j = 0; j < 12; j++) {
        apA[j] = ldp(aA, j, lane);
        apB[j] = ldp(aB, j, lane);
    }
    #pragma unroll
    for (int f = 0; f < 8; f++) {
        const float* wr = w0 + f*24;
        accA[f] = 0ULL; accB[f] = 0ULL;
        #pragma unroll
        for (int q = 0; q < 6; q++) {
            ull wa, wb; ldg2(wr + 4*q, wa, wb);
            accA[f] = ffma2(apA[2*q],     wa, accA[f]);
            accA[f] = ffma2(apA[2*q + 1], wb, accA[f]);
            accB[f] = ffma2(apB[2*q],     wa, accB[f]);
            accB[f] = ffma2(apB[2*q + 1], wb, accB[f]);
        }
    }
}

// layernorm per item over feature dim (paired layout); tid2 = tid & 255
__device__ __forceinline__ void ln_T(float* bufT, const float* __restrict__ g,
                                     const float* __restrict__ be, float* red,
                                     int tid2) {
    const int t = tid2 & 31, w = tid2 >> 5;
    float vx[16]; float s = 0.f, q = 0.f;
    #pragma unroll
    for (int jj = 0; jj < 8; jj++) {
        ull vp = ldp(bufT, w*8 + jj, t);
        up2(vp, vx[2*jj], vx[2*jj+1]);
        s += vx[2*jj] + vx[2*jj+1];
        q += vx[2*jj]*vx[2*jj] + vx[2*jj+1]*vx[2*jj+1];
    }
    red[w*32 + t] = s; red[256 + w*32 + t] = q;
    __syncthreads();
    if (tid2 < 32) {
        float S = 0.f, Q = 0.f;
        #pragma unroll
        for (int r = 0; r < 8; r++) { S += red[r*32 + tid2]; Q += red[256 + r*32 + tid2]; }
        float m = S * (1.f/128.f);
        float var = Q * (1.f/128.f) - m*m;
        red[512 + tid2] = m;
        red[544 + tid2] = rsqrtf(var + 1e-5f);
    }
    __syncthreads();
    const float m = red[512 + t], rr = red[544 + t];
    #pragma unroll
    for (int jj = 0; jj < 8; jj++) {
        int d0 = w*16 + 2*jj;
        float y0 = (vx[2*jj]   - m)*rr*g[d0]   + be[d0];
        float y1 = (vx[2*jj+1] - m)*rr*g[d0+1] + be[d0+1];
        stp(bufT, w*8 + jj, t, pk(y0, y1));
    }
}

__global__ __launch_bounds__(NT, 1)
void ts_kernel(const float* __restrict__ z,
               const float* __restrict__ WPw, const float* __restrict__ WPb,
               const float* __restrict__ PE,  const float* __restrict__ dummies,
               const float* __restrict__ Wq,  const float* __restrict__ bq,
               const float* __restrict__ Wk,  const float* __restrict__ bk,
               const float* __restrict__ Wv,  const float* __restrict__ bv,
               const float* __restrict__ Wo,  const float* __restrict__ bo,
               const float* __restrict__ g1,  const float* __restrict__ be1,
               const float* __restrict__ W1,  const float* __restrict__ b1,
               const float* __restrict__ W2,  const float* __restrict__ b2,
               const float* __restrict__ g2,  const float* __restrict__ be2,
               const float* __restrict__ Pw,  const float* __restrict__ Pb,
               float* __restrict__ out)
{
    extern __shared__ float sm[];
    float* xT  = sm + OFF_XT;
    float* prT = sm + OFF_PRT;
    float* kT  = sm + OFF_KT;
    float* vT  = sm + OFF_VT;
    float* scr = sm + OFF_SCR;

    const int tid  = threadIdx.x;
    const int wid  = tid >> 5;
    const int lane = tid & 31;
    const int f0   = wid * 8;
    const int fp0  = wid * 4;          // first feature-pair index
    const int blk  = blockIdx.x;

    const int half = tid >> 8;
    const int tid2 = tid & 255;
    const int item = blk*2 + half;
    const int chn  = item % CIN;
    const float* zr = z + (size_t)item * SEQ;
    float* hb = sm + half * ISTR;

    const uint32_t slot =
        (uint32_t)__cvta_generic_to_shared(sm + OFF_STG) + (uint32_t)wid * 1024u;

    fillc(slot, Wk, f0, 0, 0, lane);

    // -------- instance stats (per item) --------
    float* redh = hb + OFF_SCR;
    float s1 = 0.f, s2 = 0.f;
    for (int i = tid2; i < SEQ; i += 256) { float v = zr[i]; s1 += v; s2 += v*v; }
    #pragma unroll
    for (int o = 16; o; o >>= 1) {
        s1 += __shfl_xor_sync(0xffffffffu, s1, o);
        s2 += __shfl_xor_sync(0xffffffffu, s2, o);
    }
    if (lane == 0) { redh[tid2 >> 5] = s1; redh[8 + (tid2 >> 5)] = s2; }
    __syncthreads();
    if (tid2 == 0) {
        float S1 = 0.f, S2 = 0.f;
        #pragma unroll
        for (int w = 0; w < 8; w++) { S1 += redh[w]; S2 += redh[8 + w]; }
        float m   = S1 / (float)SEQ;
        float var = S2 / (float)SEQ - m*m;
        float sd  = sqrtf(var + 1e-5f);
        redh[16] = m; redh[17] = 1.f/sd; redh[18] = sd;
    }
    __syncthreads();
    const float mu = redh[16], rstd = redh[17], sd = redh[18];
    __syncthreads();

    // -------- stage znT patches (paired) into item's vT; PE into item-A kT --------
    for (int i = tid2; i < SEQ; i += 256) {
        int s = i / 24, p = i - s*24;
        hb[OFF_VT + ((p>>1)*TP + s)*2 + (p&1)] = (zr[i] - mu) * rstd;
    }
    for (int i = tid; i < PN*128; i += NT) {
        int s = i >> 7, d = i & 127;
        kT[((d>>1)*TP + s)*2 + (d&1)] = PE[i];
    }
    __syncthreads();

    // -------- patch embedding: x = W_P*patches + b + PE (dual) --------
    {
        ull aA[8], aB[8];
        accum8p2(vT, vT + ISTR, WPw + f0*24, lane, aA, aB);
        if (lane < PN) {
            #pragma unroll
            for (int j = 0; j < 4; j++) {
                float pe0, pe1; up2(ldp(kT, fp0 + j, lane), pe0, pe1);
                float b0 = WPb[f0 + 2*j], b1v = WPb[f0 + 2*j + 1];
                stp(xT,        fp0 + j, lane, pk(fin(aA[2*j]) + b0 + pe0, fin(aA[2*j+1]) + b1v + pe1));
                stp(xT + ISTR, fp0 + j, lane, pk(fin(aB[2*j]) + b0 + pe0, fin(aB[2*j+1]) + b1v + pe1));
            }
        }
    }
    __syncthreads();
    // -------- pred from dummies --------
    {
        const float* dm = dummies + (size_t)chn * PN * 24;
        for (int i = tid2; i < PN*24; i += 256) {
            int s = i / 24, p = i - s*24;
            hb[OFF_VT + ((p>>1)*TP + s)*2 + (p&1)] = dm[i];
        }
        __syncthreads();
        ull aA[8], aB[8];
        accum8p2(vT, vT + ISTR, WPw + f0*24, lane, aA, aB);
        if (lane < PN) {
            #pragma unroll
            for (int j = 0; j < 4; j++) {
                float b0 = WPb[f0 + 2*j], b1v = WPb[f0 + 2*j + 1];
                stp(prT,        fp0 + j, lane, pk(fin(aA[2*j]) + b0, fin(aA[2*j+1]) + b1v));
                stp(prT + ISTR, fp0 + j, lane, pk(fin(aB[2*j]) + b0, fin(aB[2*j+1]) + b1v));
            }
        }
    }
    __syncthreads();

    // -------- transformer layers --------
    #pragma unroll 1
    for (int L = 0; L < 3; L++) {
        const size_t o128 = (size_t)L * 16384;
        const float* w1a = W1 + (size_t)L * 32768;
        const float* w1g = w1a + 16384;

        // ---- K ----
        {
            ull aA[8], aB[8];
            accum8d2(xT, xT + ISTR, Wk + o128, Wv + o128, true, slot, f0, lane, aA, aB);
            if (lane < PN) {
                #pragma unroll
                for (int j = 0; j < 4; j++) {
                    float b0 = bk[L*128 + f0 + 2*j], b1v = bk[L*128 + f0 + 2*j + 1];
                    stp(kT,        fp0 + j, lane, pk(fin(aA[2*j]) + b0, fin(aA[2*j+1]) + b1v));
                    stp(kT + ISTR, fp0 + j, lane, pk(fin(aB[2*j]) + b0, fin(aB[2*j+1]) + b1v));
                }
            }
        }
        // ---- V ----
        {
            ull aA[8], aB[8];
            accum8d2(xT, xT + ISTR, Wv + o128, Wq + o128, true, slot, f0, lane, aA, aB);
            if (lane < PN) {
                #pragma unroll
                for (int j = 0; j < 4; j++) {
                    float b0 = bv[L*128 + f0 + 2*j], b1v = bv[L*128 + f0 + 2*j + 1];
                    stp(vT,        fp0 + j, lane, pk(fin(aA[2*j]) + b0, fin(aA[2*j+1]) + b1v));
                    stp(vT + ISTR, fp0 + j, lane, pk(fin(aB[2*j]) + b0, fin(aB[2*j+1]) + b1v));
                }
            }
        }
        // ---- Q -> scr ----
        {
            ull aA[8], aB[8];
            accum8d2(prT, prT + ISTR, Wq + o128, Wo + o128, true, slot, f0, lane, aA, aB);
            if (lane < PN) {
                #pragma unroll
                for (int j = 0; j < 4; j++) {
                    float b0 = bq[L*128 + f0 + 2*j], b1v = bq[L*128 + f0 + 2*j + 1];
                    stp(scr,        fp0 + j, lane, pk(fin(aA[2*j]) + b0, fin(aA[2*j+1]) + b1v));
                    stp(scr + ISTR, fp0 + j, lane, pk(fin(aB[2*j]) + b0, fin(aB[2*j+1]) + b1v));
                }
            }
        }
        __syncthreads();

        // ---- attention: thread per (h,p,item); f32x2 dot + online softmax ----
        for (int rr = tid; rr < 2*NROW; rr += NT) {
            const int it = rr >= NROW;
            const int r0 = rr - it*NROW;
            const int h = r0 / PN, p = r0 - h*PN;
            float* ib = sm + it * ISTR;
            float* sg = scoG + (size_t)(blk*2 + it) * (PN*NROW) + r0;
            ull qp[4];
            #pragma unroll
            for (int jj = 0; jj < 4; jj++) qp[jj] = ldp(ib + OFF_SCR, h*4 + jj, p);
            float m = -1e30f, ssum = 0.f;
            #pragma unroll 1
            for (int t = 0; t < PN; t++) {
                ull d2 = 0ULL;
                #pragma unroll
                for (int jj = 0; jj < 4; jj++)
                    d2 = ffma2(qp[jj], ldp(ib + OFF_KT, h*4 + jj, t), d2);
                float s = fin(d2) * SCALEF;
                if (L) s += sg[t*NROW];
                sg[t*NROW] = s;
                float mn = fmaxf(m, s);
                ssum = ssum * __expf(m - mn) + __expf(s - mn);
                m = mn;
            }
            const float inv = 1.f / ssum;
            ull ov[4];
            #pragma unroll
            for (int jj = 0; jj < 4; jj++) ov[jj] = 0ULL;
            #pragma unroll 1
            for (int t = 0; t < PN; t++) {
                float w = __expf(sg[t*NROW] - m);
                ull wp = pk(w, w);
                #pragma unroll
                for (int jj = 0; jj < 4; jj++)
                    ov[jj] = ffma2(wp, ldp(ib + OFF_VT, h*4 + jj, t), ov[jj]);
            }
            #pragma unroll
            for (int jj = 0; jj < 4; jj++) {
                float o0, o1; up2(ov[jj], o0, o1);
                stp(ib + OFF_SCR, h*4 + jj, p, pk(o0*inv, o1*inv));
            }
        }
        __syncthreads();

        // ---- O + residual ----
        {
            ull aA[8], aB[8];
            accum8d2(scr, scr + ISTR, Wo + o128, w1a, true, slot, f0, lane, aA, aB);
            if (lane < PN) {
                #pragma unroll
                for (int j = 0; j < 4; j++) {
                    float b0 = bo[L*128 + f0 + 2*j], b1v = bo[L*128 + f0 + 2*j + 1];
                    float pA0, pA1, pB0, pB1;
                    up2(ldp(prT,        fp0 + j, lane), pA0, pA1);
                    up2(ldp(prT + ISTR, fp0 + j, lane), pB0, pB1);
                    stp(prT,        fp0 + j, lane, pk(pA0 + fin(aA[2*j]) + b0, pA1 + fin(aA[2*j+1]) + b1v));
                    stp(prT + ISTR, fp0 + j, lane, pk(pB0 + fin(aB[2*j]) + b0, pB1 + fin(aB[2*j+1]) + b1v));
                }
            }
        }
        __syncthreads();
        ln_T(hb + OFF_PRT, g1 + L*128, be1 + L*128, hb + OFF_SCR, tid2);
        __syncthreads();

        // ---- FFN up a-half -> vT ----
        {
            ull aA[8], aB[8];
            accum8d2(prT, prT + ISTR, w1a, w1g, true, slot, f0, lane, aA, aB);
            if (lane < PN) {
                #pragma unroll
                for (int j = 0; j < 4; j++) {
                    float b0 = b1[L*256 + f0 + 2*j], b1v = b1[L*256 + f0 + 2*j + 1];
                    stp(vT,        fp0 + j, lane, pk(fin(aA[2*j]) + b0, fin(aA[2*j+1]) + b1v));
                    stp(vT + ISTR, fp0 + j, lane, pk(fin(aB[2*j]) + b0, fin(aB[2*j+1]) + b1v));
                }
            }
        }
        // ---- FFN up gate-half; gelu combine -> kT ----
        {
            ull aA[8], aB[8];
            accum8d2(prT, prT + ISTR, w1g, W2 + o128, true, slot, f0, lane, aA, aB);
            if (lane < PN) {
                #pragma unroll
                for (int j = 0; j < 4; j++) {
                    float b0 = b1[L*256 + 128 + f0 + 2*j], b1v = b1[L*256 + 128 + f0 + 2*j + 1];
                    float gA0 = fin(aA[2*j]) + b0,  gA1 = fin(aA[2*j+1]) + b1v;
                    float gB0 = fin(aB[2*j]) + b0,  gB1 = fin(aB[2*j+1]) + b1v;
                    float eA0 = 0.5f*gA0*(1.f + erff(gA0*0.70710678118654752f));
                    float eA1 = 0.5f*gA1*(1.f + erff(gA1*0.70710678118654752f));
                    float eB0 = 0.5f*gB0*(1.f + erff(gB0*0.70710678118654752f));
                    float eB1 = 0.5f*gB1*(1.f + erff(gB1*0.70710678118654752f));
                    float vA0, vA1, vB0, vB1;
                    up2(ldp(vT,        fp0 + j, lane), vA0, vA1);
                    up2(ldp(vT + ISTR, fp0 + j, lane), vB0, vB1);
                    stp(kT,        fp0 + j, lane, pk(vA0*eA0, vA1*eA1));
                    stp(kT + ISTR, fp0 + j, lane, pk(vB0*eB0, vB1*eB1));
                }
            }
        }
        __syncthreads();

        // ---- FFN down + residual ----
        {
            ull aA[8], aB[8];
            accum8d2(kT, kT + ISTR, W2 + o128, Wk + (size_t)(L+1)*16384, L < 2,
                     slot, f0, lane, aA, aB);
            if (lane < PN) {
                #pragma unroll
                for (int j = 0; j < 4; j++) {
                    float b0 = b2[L*128 + f0 + 2*j], b1v = b2[L*128 + f0 + 2*j + 1];
                    float pA0, pA1, pB0, pB1;
                    up2(ldp(prT,        fp0 + j, lane), pA0, pA1);
                    up2(ldp(prT + ISTR, fp0 + j, lane), pB0, pB1);
                    stp(prT,        fp0 + j, lane, pk(pA0 + fin(aA[2*j]) + b0, pA1 + fin(aA[2*j+1]) + b1v));
                    stp(prT + ISTR, fp0 + j, lane, pk(pB0 + fin(aB[2*j]) + b0, pB1 + fin(aB[2*j+1]) + b1v));
                }
            }
        }
        __syncthreads();
        ln_T(hb + OFF_PRT, g2 + L*128, be2 + L*128, hb + OFF_SCR, tid2);
        __syncthreads();
    }

    // -------- output head: warp-halves per item, 3 patch-lanes/warp --------
    {
        const int hit  = wid >> 3;
        const int pl0  = (wid & 7) * 3;
        const float* pT = sm + hit*ISTR + OFF_PRT;
        float* outb     = sm + hit*ISTR + OFF_SCR;
        ull a0 = 0ULL, a1 = 0ULL, a2 = 0ULL;
        #pragma unroll 2
        for (int c = 0; c < 8; c++) {
            ull ap[8];
            #pragma unroll
            for (int j = 0; j < 8; j++)
                ap[j] = ldp(pT, c*8 + j, lane);
            const float* wr0 = Pw + (pl0    )*128 + c*16;
            const float* wr1 = Pw + (pl0 + 1)*128 + c*16;
            const float* wr2 = Pw + (pl0 + 2)*128 + c*16;
            #pragma unroll
            for (int q = 0; q < 4; q++) {
                ull wa, wb;
                ldg2(wr0 + 4*q, wa, wb);
                a0 = ffma2(ap[2*q], wa, a0); a0 = ffma2(ap[2*q+1], wb, a0);
                ldg2(wr1 + 4*q, wa, wb);
                a1 = ffma2(ap[2*q], wa, a1); a1 = ffma2(ap[2*q+1], wb, a1);
                ldg2(wr2 + 4*q, wa, wb);
                a2 = ffma2(ap[2*q], wa, a2); a2 = ffma2(ap[2*q+1], wb, a2);
            }
        }
        if (lane < PN) {
            outb[lane*24 + pl0    ] = fin(a0) + Pb[pl0];
            outb[lane*24 + pl0 + 1] = fin(a1) + Pb[pl0 + 1];
            outb[lane*24 + pl0 + 2] = fin(a2) + Pb[pl0 + 2];
        }
    }
    __syncthreads();
    {
        const float* outb = hb + OFF_SCR;
        for (int i = tid2; i < SEQ; i += 256)
            out[(size_t)item*SEQ + i] = outb[i]*sd + mu;
    }
}

extern "C" void kernel_launch(void* const* d_in, const int* in_sizes, int n_in,
                              void* d_out, int out_size)
{
    (void)in_sizes; (void)n_in; (void)out_size;
    cudaFuncSetAttribute(ts_kernel, cudaFuncAttributeMaxDynamicSharedMemorySize, SMEM_BYTES);
    ts_kernel<<<ITEMS/2, NT, SMEM_BYTES>>>(
        (const float*)d_in[0],  (const float*)d_in[1],  (const float*)d_in[2],
        (const float*)d_in[3],  (const float*)d_in[4],  (const float*)d_in[5],
        (const float*)d_in[6],  (const float*)d_in[7],  (const float*)d_in[8],
        (const float*)d_in[9],  (const float*)d_in[10], (const float*)d_in[11],
        (const float*)d_in[12], (const float*)d_in[13], (const float*)d_in[14],
        (const float*)d_in[15], (const float*)d_in[16], (const float*)d_in[17],
        (const float*)d_in[18], (const float*)d_in[19], (const float*)d_in[20],
        (const float*)d_in[21], (const float*)d_in[22],
        (float*)d_out);
}

// round 12
// speedup vs baseline: 3.4898x; 1.1589x over previous
#include <cuda_runtime.h>
#include <cstdint>
#include <math.h>

#define NT     512
#define PN     30
#define TP     33            // pair-row stride (in float2 units)
#define CIN    321
#define SEQ    720
#define NROW   480
#define ITEMS  5136
#define ISTR   21120
#define SCALEF 0.35355339059327373f   // 8^-0.5

typedef unsigned long long ull;

// persistent raw-score scratch: [item][t(30)][row(480)]
__device__ float scoG[(size_t)ITEMS * PN * NROW];

// ---------- packed f32x2 helpers ----------
__device__ __forceinline__ ull pk(float lo, float hi) {
    ull r; asm("mov.b64 %0, {%1, %2};" : "=l"(r) : "f"(lo), "f"(hi)); return r;
}
__device__ __forceinline__ float fin(ull a) {
    float x, y; asm("mov.b64 {%0, %1}, %2;" : "=f"(x), "=f"(y) : "l"(a)); return x + y;
}
__device__ __forceinline__ void up2(ull a, float& x, float& y) {
    asm("mov.b64 {%0, %1}, %2;" : "=f"(x), "=f"(y) : "l"(a));
}
__device__ __forceinline__ ull ffma2(ull a, ull b, ull c) {
    ull d; asm("fma.rn.f32x2 %0, %1, %2, %3;" : "=l"(d) : "l"(a), "l"(b), "l"(c)); return d;
}
__device__ __forceinline__ void ldg2(const float* p, ull& a, ull& b) {
    asm("ld.global.nc.v2.u64 {%0, %1}, [%2];" : "=l"(a), "=l"(b) : "l"(p));
}
__device__ __forceinline__ void lds2(uint32_t a32, ull& a, ull& b) {
    asm volatile("ld.shared.v2.u64 {%0, %1}, [%2];"
                 : "=l"(a), "=l"(b) : "r"(a32) : "memory");
}
// paired activation accessors: buffer holds [64 pairs][TP tokens] float2
__device__ __forceinline__ ull ldp(const float* b, int fp, int t) {
    return *(const ull*)(b + (fp*TP + t)*2);
}
__device__ __forceinline__ void stp(float* b, int fp, int t, ull v) {
    *(ull*)(b + (fp*TP + t)*2) = v;
}

// ---------- smem layout (floats) ----------
// per item (stride ISTR): xT 0 | prT 4224 | kT 8448 | vT 12672 | scr 16896
#define OFF_XT   0
#define OFF_PRT  4224
#define OFF_KT   8448
#define OFF_VT   12672
#define OFF_SCR  16896
#define OFF_STG  42240       // 16 warps x 512 floats (ring of 4 x 512B)
#define SMEM_FLOATS (42240 + 8192)
#define SMEM_BYTES  (SMEM_FLOATS * 4)    // 201,728 B -> 1 CTA/SM

// ---------- async weight staging: ring of 4 x 512B per warp, depth-2 prefetch ----------
__device__ __forceinline__ void fillc(uint32_t slot, const float* __restrict__ W,
                                      int f0, int ch, int buf, int lane) {
    int r = lane >> 2, o = lane & 3;
    uint32_t dst = slot + (uint32_t)(buf*512 + r*64 + o*16);
    const float* src = W + (size_t)(f0 + r)*128 + ch*16 + o*4;
    asm volatile("cp.async.cg.shared.global [%0], [%1], 16;"
                 :: "r"(dst), "l"(src) : "memory");
    asm volatile("cp.async.commit_group;" ::: "memory");
}
__device__ __forceinline__ void waitg2() {
    asm volatile("cp.async.wait_group 2;" ::: "memory");
    __syncwarp();
}
__device__ __forceinline__ void waitg1() {
    asm volatile("cp.async.wait_group 1;" ::: "memory");
    __syncwarp();
}
__device__ __forceinline__ void waitg0() {
    asm volatile("cp.async.wait_group 0;" ::: "memory");
    __syncwarp();
}

// warp computes 8 output features (rows f0..f0+7, K=128) for BOTH items.
// entry invariant: fills for Wc chunks 0 (buf0) and 1 (buf1) committed, <=2 pending.
// exit invariant (donext): fills for Wn chunks 0 (buf0) and 1 (buf1) committed.
__device__ __forceinline__ void accum8d2(const float* __restrict__ aA,
                                         const float* __restrict__ aB,
                                         const float* __restrict__ Wc,
                                         const float* __restrict__ Wn, bool donext,
                                         uint32_t slot, int f0, int lane,
                                         ull accA[8], ull accB[8]) {
    #pragma unroll
    for (int j = 0; j < 8; j++) { accA[j] = 0ULL; accB[j] = 0ULL; }
    #pragma unroll 1
    for (int ch = 0; ch < 8; ch++) {
        if (ch < 6)      { fillc(slot, Wc, f0, ch + 2, (ch + 2) & 3, lane); waitg2(); }
        else if (donext) { fillc(slot, Wn, f0, ch - 6, (ch + 2) & 3, lane); waitg2(); }
        else if (ch == 6)  waitg1();
        else               waitg0();

        ull apA[8], apB[8];
        #pragma unroll
        for (int j = 0; j < 8; j++) {
            apA[j] = ldp(aA, ch*8 + j, lane);
            apB[j] = ldp(aB, ch*8 + j, lane);
        }
        const uint32_t base = slot + (uint32_t)((ch & 3) * 512);
        #pragma unroll
        for (int f = 0; f < 8; f++) {
            uint32_t wr = base + (uint32_t)(f * 64);
            ull w0,w1,w2,w3,w4,w5,w6,w7;
            lds2(wr,      w0, w1);
            lds2(wr + 16, w2, w3);
            lds2(wr + 32, w4, w5);
            lds2(wr + 48, w6, w7);
            accA[f] = ffma2(apA[0], w0, accA[f]);
            accA[f] = ffma2(apA[1], w1, accA[f]);
            accA[f] = ffma2(apA[2], w2, accA[f]);
            accA[f] = ffma2(apA[3], w3, accA[f]);
            accA[f] = ffma2(apA[4], w4, accA[f]);
            accA[f] = ffma2(apA[5], w5, accA[f]);
            accA[f] = ffma2(apA[6], w6, accA[f]);
            accA[f] = ffma2(apA[7], w7, accA[f]);
            accB[f] = ffma2(apB[0], w0, accB[f]);
            accB[f] = ffma2(apB[1], w1, accB[f]);
            accB[f] = ffma2(apB[2], w2, accB[f]);
            accB[f] = ffma2(apB[3], w3, accB[f]);
            accB[f] = ffma2(apB[4], w4, accB[f]);
            accB[f] = ffma2(apB[5], w5, accB[f]);
            accB[f] = ffma2(apB[6], w6, accB[f]);
            accB[f] = ffma2(apB[7], w7, accB[f]);
        }
    }
}

// patch embedding: 8 features, K = 24 (12 pairs), dual item, weights via LDG
__device__ __forceinline__ void accum8p2(const float* __restrict__ aA,
                                         const float* __restrict__ aB,
                                         const float* __restrict__ w0,
                                         int lane, ull accA[8], ull accB[8]) {
    ull apA[12], apB[12];
    #pragma unroll
    for (int j = 0; j < 12; j++) {
        apA[j] = ldp(aA, j, lane);
        apB[j] = ldp(aB, j, lane);
    }
    #pragma unroll
    for (int f = 0; f < 8; f++) {
        const float* wr = w0 + f*24;
        accA[f] = 0ULL; accB[f] = 0ULL;
        #pragma unroll
        for (int q = 0; q < 6; q++) {
            ull wa, wb; ldg2(wr + 4*q, wa, wb);
            accA[f] = ffma2(apA[2*q],     wa, accA[f]);
            accA[f] = ffma2(apA[2*q + 1], wb, accA[f]);
            accB[f] = ffma2(apB[2*q],     wa, accB[f]);
            accB[f] = ffma2(apB[2*q + 1], wb, accB[f]);
        }
    }
}

// layernorm per item over feature dim (paired layout); tid2 = tid & 255
__device__ __forceinline__ void ln_T(float* bufT, const float* __restrict__ g,
                                     const float* __restrict__ be, float* red,
                                     int tid2) {
    const int t = tid2 & 31, w = tid2 >> 5;
    float vx[16]; float s = 0.f, q = 0.f;
    #pragma unroll
    for (int jj = 0; jj < 8; jj++) {
        ull vp = ldp(bufT, w*8 + jj, t);
        up2(vp, vx[2*jj], vx[2*jj+1]);
        s += vx[2*jj] + vx[2*jj+1];
        q += vx[2*jj]*vx[2*jj] + vx[2*jj+1]*vx[2*jj+1];
    }
    red[w*32 + t] = s; red[256 + w*32 + t] = q;
    __syncthreads();
    if (tid2 < 32) {
        float S = 0.f, Q = 0.f;
        #pragma unroll
        for (int r = 0; r < 8; r++) { S += red[r*32 + tid2]; Q += red[256 + r*32 + tid2]; }
        float m = S * (1.f/128.f);
        float var = Q * (1.f/128.f) - m*m;
        red[512 + tid2] = m;
        red[544 + tid2] = rsqrtf(var + 1e-5f);
    }
    __syncthreads();
    const float m = red[512 + t], rr = red[544 + t];
    #pragma unroll
    for (int jj = 0; jj < 8; jj++) {
        int d0 = w*16 + 2*jj;
        float y0 = (vx[2*jj]   - m)*rr*g[d0]   + be[d0];
        float y1 = (vx[2*jj+1] - m)*rr*g[d0+1] + be[d0+1];
        stp(bufT, w*8 + jj, t, pk(y0, y1));
    }
}

__global__ __launch_bounds__(NT, 1)
void ts_kernel(const float* __restrict__ z,
               const float* __restrict__ WPw, const float* __restrict__ WPb,
               const float* __restrict__ PE,  const float* __restrict__ dummies,
               const float* __restrict__ Wq,  const float* __restrict__ bq,
               const float* __restrict__ Wk,  const float* __restrict__ bk,
               const float* __restrict__ Wv,  const float* __restrict__ bv,
               const float* __restrict__ Wo,  const float* __restrict__ bo,
               const float* __restrict__ g1,  const float* __restrict__ be1,
               const float* __restrict__ W1,  const float* __restrict__ b1,
               const float* __restrict__ W2,  const float* __restrict__ b2,
               const float* __restrict__ g2,  const float* __restrict__ be2,
               const float* __restrict__ Pw,  const float* __restrict__ Pb,
               float* __restrict__ out)
{
    extern __shared__ float sm[];
    float* xT  = sm + OFF_XT;
    float* prT = sm + OFF_PRT;
    float* kT  = sm + OFF_KT;
    float* vT  = sm + OFF_VT;
    float* scr = sm + OFF_SCR;

    const int tid  = threadIdx.x;
    const int wid  = tid >> 5;
    const int lane = tid & 31;
    const int f0   = wid * 8;
    const int fp0  = wid * 4;
    const int blk  = blockIdx.x;

    const int half = tid >> 8;
    const int tid2 = tid & 255;
    const int item = blk*2 + half;
    const int chn  = item % CIN;
    const float* zr = z + (size_t)item * SEQ;
    float* hb = sm + half * ISTR;

    const uint32_t slot =
        (uint32_t)__cvta_generic_to_shared(sm + OFF_STG) + (uint32_t)wid * 2048u;

    // prefetch layer-0 Wk chunks 0,1 -> bufs 0,1
    fillc(slot, Wk, f0, 0, 0, lane);
    fillc(slot, Wk, f0, 1, 1, lane);

    // -------- instance stats (per item) --------
    float* redh = hb + OFF_SCR;
    float s1 = 0.f, s2 = 0.f;
    for (int i = tid2; i < SEQ; i += 256) { float v = zr[i]; s1 += v; s2 += v*v; }
    #pragma unroll
    for (int o = 16; o; o >>= 1) {
        s1 += __shfl_xor_sync(0xffffffffu, s1, o);
        s2 += __shfl_xor_sync(0xffffffffu, s2, o);
    }
    if (lane == 0) { redh[tid2 >> 5] = s1; redh[8 + (tid2 >> 5)] = s2; }
    __syncthreads();
    if (tid2 == 0) {
        float S1 = 0.f, S2 = 0.f;
        #pragma unroll
        for (int w = 0; w < 8; w++) { S1 += redh[w]; S2 += redh[8 + w]; }
        float m   = S1 / (float)SEQ;
        float var = S2 / (float)SEQ - m*m;
        float sd  = sqrtf(var + 1e-5f);
        redh[16] = m; redh[17] = 1.f/sd; redh[18] = sd;
    }
    __syncthreads();
    const float mu = redh[16], rstd = redh[17], sd = redh[18];
    __syncthreads();

    // -------- stage znT patches (paired) into item's vT; PE into item-A kT --------
    for (int i = tid2; i < SEQ; i += 256) {
        int s = i / 24, p = i - s*24;
        hb[OFF_VT + ((p>>1)*TP + s)*2 + (p&1)] = (zr[i] - mu) * rstd;
    }
    for (int i = tid; i < PN*128; i += NT) {
        int s = i >> 7, d = i & 127;
        kT[((d>>1)*TP + s)*2 + (d&1)] = PE[i];
    }
    __syncthreads();

    // -------- patch embedding: x = W_P*patches + b + PE (dual) --------
    {
        ull aA[8], aB[8];
        accum8p2(vT, vT + ISTR, WPw + f0*24, lane, aA, aB);
        if (lane < PN) {
            #pragma unroll
            for (int j = 0; j < 4; j++) {
                float pe0, pe1; up2(ldp(kT, fp0 + j, lane), pe0, pe1);
                float b0 = WPb[f0 + 2*j], b1v = WPb[f0 + 2*j + 1];
                stp(xT,        fp0 + j, lane, pk(fin(aA[2*j]) + b0 + pe0, fin(aA[2*j+1]) + b1v + pe1));
                stp(xT + ISTR, fp0 + j, lane, pk(fin(aB[2*j]) + b0 + pe0, fin(aB[2*j+1]) + b1v + pe1));
            }
        }
    }
    __syncthreads();
    // -------- pred from dummies --------
    {
        const float* dm = dummies + (size_t)chn * PN * 24;
        for (int i = tid2; i < PN*24; i += 256) {
            int s = i / 24, p = i - s*24;
            hb[OFF_VT + ((p>>1)*TP + s)*2 + (p&1)] = dm[i];
        }
        __syncthreads();
        ull aA[8], aB[8];
        accum8p2(vT, vT + ISTR, WPw + f0*24, lane, aA, aB);
        if (lane < PN) {
            #pragma unroll
            for (int j = 0; j < 4; j++) {
                float b0 = WPb[f0 + 2*j], b1v = WPb[f0 + 2*j + 1];
                stp(prT,        fp0 + j, lane, pk(fin(aA[2*j]) + b0, fin(aA[2*j+1]) + b1v));
                stp(prT + ISTR, fp0 + j, lane, pk(fin(aB[2*j]) + b0, fin(aB[2*j+1]) + b1v));
            }
        }
    }
    __syncthreads();

    // -------- transformer layers --------
    #pragma unroll 1
    for (int L = 0; L < 3; L++) {
        const size_t o128 = (size_t)L * 16384;
        const float* w1a = W1 + (size_t)L * 32768;
        const float* w1g = w1a + 16384;

        // ---- K ----
        {
            ull aA[8], aB[8];
            accum8d2(xT, xT + ISTR, Wk + o128, Wv + o128, true, slot, f0, lane, aA, aB);
            if (lane < PN) {
                #pragma unroll
                for (int j = 0; j < 4; j++) {
                    float b0 = bk[L*128 + f0 + 2*j], b1v = bk[L*128 + f0 + 2*j + 1];
                    stp(kT,        fp0 + j, lane, pk(fin(aA[2*j]) + b0, fin(aA[2*j+1]) + b1v));
                    stp(kT + ISTR, fp0 + j, lane, pk(fin(aB[2*j]) + b0, fin(aB[2*j+1]) + b1v));
                }
            }
        }
        // ---- V ----
        {
            ull aA[8], aB[8];
            accum8d2(xT, xT + ISTR, Wv + o128, Wq + o128, true, slot, f0, lane, aA, aB);
            if (lane < PN) {
                #pragma unroll
                for (int j = 0; j < 4; j++) {
                    float b0 = bv[L*128 + f0 + 2*j], b1v = bv[L*128 + f0 + 2*j + 1];
                    stp(vT,        fp0 + j, lane, pk(fin(aA[2*j]) + b0, fin(aA[2*j+1]) + b1v));
                    stp(vT + ISTR, fp0 + j, lane, pk(fin(aB[2*j]) + b0, fin(aB[2*j+1]) + b1v));
                }
            }
        }
        // ---- Q -> scr ----
        {
            ull aA[8], aB[8];
            accum8d2(prT, prT + ISTR, Wq + o128, Wo + o128, true, slot, f0, lane, aA, aB);
            if (lane < PN) {
                #pragma unroll
                for (int j = 0; j < 4; j++) {
                    float b0 = bq[L*128 + f0 + 2*j], b1v = bq[L*128 + f0 + 2*j + 1];
                    stp(scr,        fp0 + j, lane, pk(fin(aA[2*j]) + b0, fin(aA[2*j+1]) + b1v));
                    stp(scr + ISTR, fp0 + j, lane, pk(fin(aB[2*j]) + b0, fin(aB[2*j+1]) + b1v));
                }
            }
        }
        __syncthreads();

        // ---- attention: thread per (h,p,item); scores kept in registers ----
        for (int rr = tid; rr < 2*NROW; rr += NT) {
            const int it = rr >= NROW;
            const int r0 = rr - it*NROW;
            const int h = r0 / PN, p = r0 - h*PN;
            float* ib = sm + it * ISTR;
            float* sg = scoG + (size_t)(blk*2 + it) * (PN*NROW) + r0;
            ull qp[4];
            #pragma unroll
            for (int jj = 0; jj < 4; jj++) qp[jj] = ldp(ib + OFF_SCR, h*4 + jj, p);
            float sreg[PN];
            float m = -1e30f;
            #pragma unroll
            for (int t = 0; t < PN; t++) {
                ull d2 = 0ULL;
                #pragma unroll
                for (int jj = 0; jj < 4; jj++)
                    d2 = ffma2(qp[jj], ldp(ib + OFF_KT, h*4 + jj, t), d2);
                float s = fin(d2) * SCALEF;
                if (L) s += sg[t*NROW];
                sg[t*NROW] = s;
                sreg[t] = s;
                m = fmaxf(m, s);
            }
            float ssum = 0.f;
            #pragma unroll
            for (int t = 0; t < PN; t++) {
                float w = __expf(sreg[t] - m);
                sreg[t] = w;
                ssum += w;
            }
            const float inv = 1.f / ssum;
            ull ov[4];
            #pragma unroll
            for (int jj = 0; jj < 4; jj++) ov[jj] = 0ULL;
            #pragma unroll
            for (int t = 0; t < PN; t++) {
                ull wp = pk(sreg[t], sreg[t]);
                #pragma unroll
                for (int jj = 0; jj < 4; jj++)
                    ov[jj] = ffma2(wp, ldp(ib + OFF_VT, h*4 + jj, t), ov[jj]);
            }
            #pragma unroll
            for (int jj = 0; jj < 4; jj++) {
                float o0, o1; up2(ov[jj], o0, o1);
                stp(ib + OFF_SCR, h*4 + jj, p, pk(o0*inv, o1*inv));
            }
        }
        __syncthreads();

        // ---- O + residual ----
        {
            ull aA[8], aB[8];
            accum8d2(scr, scr + ISTR, Wo + o128, w1a, true, slot, f0, lane, aA, aB);
            if (lane < PN) {
                #pragma unroll
                for (int j = 0; j < 4; j++) {
                    float b0 = bo[L*128 + f0 + 2*j], b1v = bo[L*128 + f0 + 2*j + 1];
                    float pA0, pA1, pB0, pB1;
                    up2(ldp(prT,        fp0 + j, lane), pA0, pA1);
                    up2(ldp(prT + ISTR, fp0 + j, lane), pB0, pB1);
                    stp(prT,        fp0 + j, lane, pk(pA0 + fin(aA[2*j]) + b0, pA1 + fin(aA[2*j+1]) + b1v));
                    stp(prT + ISTR, fp0 + j, lane, pk(pB0 + fin(aB[2*j]) + b0, pB1 + fin(aB[2*j+1]) + b1v));
                }
            }
        }
        __syncthreads();
        ln_T(hb + OFF_PRT, g1 + L*128, be1 + L*128, hb + OFF_SCR, tid2);
        __syncthreads();

        // ---- FFN up a-half -> vT ----
        {
            ull aA[8], aB[8];
            accum8d2(prT, prT + ISTR, w1a, w1g, true, slot, f0, lane, aA, aB);
            if (lane < PN) {
                #pragma unroll
                for (int j = 0; j < 4; j++) {
                    float b0 = b1[L*256 + f0 + 2*j], b1v = b1[L*256 + f0 + 2*j + 1];
                    stp(vT,        fp0 + j, lane, pk(fin(aA[2*j]) + b0, fin(aA[2*j+1]) + b1v));
                    stp(vT + ISTR, fp0 + j, lane, pk(fin(aB[2*j]) + b0, fin(aB[2*j+1]) + b1v));
                }
            }
        }
        // ---- FFN up gate-half; gelu combine -> kT ----
        {
            ull aA[8], aB[8];
            accum8d2(prT, prT + ISTR, w1g, W2 + o128, true, slot, f0, lane, aA, aB);
            if (lane < PN) {
                #pragma unroll
                for (int j = 0; j < 4; j++) {
                    float b0 = b1[L*256 + 128 + f0 + 2*j], b1v = b1[L*256 + 128 + f0 + 2*j + 1];
                    float gA0 = fin(aA[2*j]) + b0,  gA1 = fin(aA[2*j+1]) + b1v;
                    float gB0 = fin(aB[2*j]) + b0,  gB1 = fin(aB[2*j+1]) + b1v;
                    float eA0 = 0.5f*gA0*(1.f + erff(gA0*0.70710678118654752f));
                    float eA1 = 0.5f*gA1*(1.f + erff(gA1*0.70710678118654752f));
                    float eB0 = 0.5f*gB0*(1.f + erff(gB0*0.70710678118654752f));
                    float eB1 = 0.5f*gB1*(1.f + erff(gB1*0.70710678118654752f));
                    float vA0, vA1, vB0, vB1;
                    up2(ldp(vT,        fp0 + j, lane), vA0, vA1);
                    up2(ldp(vT + ISTR, fp0 + j, lane), vB0, vB1);
                    stp(kT,        fp0 + j, lane, pk(vA0*eA0, vA1*eA1));
                    stp(kT + ISTR, fp0 + j, lane, pk(vB0*eB0, vB1*eB1));
                }
            }
        }
        __syncthreads();

        // ---- FFN down + residual ----
        {
            ull aA[8], aB[8];
            accum8d2(kT, kT + ISTR, W2 + o128, Wk + (size_t)(L+1)*16384, L < 2,
                     slot, f0, lane, aA, aB);
            if (lane < PN) {
                #pragma unroll
                for (int j = 0; j < 4; j++) {
                    float b0 = b2[L*128 + f0 + 2*j], b1v = b2[L*128 + f0 + 2*j + 1];
                    float pA0, pA1, pB0, pB1;
                    up2(ldp(prT,        fp0 + j, lane), pA0, pA1);
                    up2(ldp(prT + ISTR, fp0 + j, lane), pB0, pB1);
                    stp(prT,        fp0 + j, lane, pk(pA0 + fin(aA[2*j]) + b0, pA1 + fin(aA[2*j+1]) + b1v));
                    stp(prT + ISTR, fp0 + j, lane, pk(pB0 + fin(aB[2*j]) + b0, pB1 + fin(aB[2*j+1]) + b1v));
                }
            }
        }
        __syncthreads();
        ln_T(hb + OFF_PRT, g2 + L*128, be2 + L*128, hb + OFF_SCR, tid2);
        __syncthreads();
    }

    // -------- output head: warp-halves per item, 3 patch-lanes/warp --------
    {
        const int hit  = wid >> 3;
        const int pl0  = (wid & 7) * 3;
        const float* pT = sm + hit*ISTR + OFF_PRT;
        float* outb     = sm + hit*ISTR + OFF_SCR;
        ull a0 = 0ULL, a1 = 0ULL, a2 = 0ULL;
        #pragma unroll 2
        for (int c = 0; c < 8; c++) {
            ull ap[8];
            #pragma unroll
            for (int j = 0; j < 8; j++)
                ap[j] = ldp(pT, c*8 + j, lane);
            const float* wr0 = Pw + (pl0    )*128 + c*16;
            const float* wr1 = Pw + (pl0 + 1)*128 + c*16;
            const float* wr2 = Pw + (pl0 + 2)*128 + c*16;
            #pragma unroll
            for (int q = 0; q < 4; q++) {
                ull wa, wb;
                ldg2(wr0 + 4*q, wa, wb);
                a0 = ffma2(ap[2*q], wa, a0); a0 = ffma2(ap[2*q+1], wb, a0);
                ldg2(wr1 + 4*q, wa, wb);
                a1 = ffma2(ap[2*q], wa, a1); a1 = ffma2(ap[2*q+1], wb, a1);
                ldg2(wr2 + 4*q, wa, wb);
                a2 = ffma2(ap[2*q], wa, a2); a2 = ffma2(ap[2*q+1], wb, a2);
            }
        }
        if (lane < PN) {
            outb[lane*24 + pl0    ] = fin(a0) + Pb[pl0];
            outb[lane*24 + pl0 + 1] = fin(a1) + Pb[pl0 + 1];
            outb[lane*24 + pl0 + 2] = fin(a2) + Pb[pl0 + 2];
        }
    }
    __syncthreads();
    {
        const float* outb = hb + OFF_SCR;
        for (int i = tid2; i < SEQ; i += 256)
            out[(size_t)item*SEQ + i] = outb[i]*sd + mu;
    }
}

extern "C" void kernel_launch(void* const* d_in, const int* in_sizes, int n_in,
                              void* d_out, int out_size)
{
    (void)in_sizes; (void)n_in; (void)out_size;
    cudaFuncSetAttribute(ts_kernel, cudaFuncAttributeMaxDynamicSharedMemorySize, SMEM_BYTES);
    ts_kernel<<<ITEMS/2, NT, SMEM_BYTES>>>(
        (const float*)d_in[0],  (const float*)d_in[1],  (const float*)d_in[2],
        (const float*)d_in[3],  (const float*)d_in[4],  (const float*)d_in[5],
        (const float*)d_in[6],  (const float*)d_in[7],  (const float*)d_in[8],
        (const float*)d_in[9],  (const float*)d_in[10], (const float*)d_in[11],
        (const float*)d_in[12], (const float*)d_in[13], (const float*)d_in[14],
        (const float*)d_in[15], (const float*)d_in[16], (const float*)d_in[17],
        (const float*)d_in[18], (const float*)d_in[19], (const float*)d_in[20],
        (const float*)d_in[21], (const float*)d_in[22],
        (float*)d_out);
}